// round 1
// baseline (speedup 1.0000x reference)
#include <cuda_runtime.h>
#include <math.h>
#include <stdint.h>

// Problem constants
#define BB   8
#define NN   8192
#define SS   2048
#define DD   256
#define MM   65536      // BB*NN
#define H0   256
#define H1   128
#define K0   512        // 2*DD
#define BNEPS 1e-5f

// ---------------------------------------------------------------------------
// Scratch (device globals; no dynamic allocation allowed)
// ---------------------------------------------------------------------------
__device__ float  g_h [(size_t)MM * K0];   // concat(points1, interp)  [M, 512]
__device__ float  g_y0[(size_t)MM * H0];   // layer0 pre-BN output     [M, 256]
__device__ int    g_idx[MM * 3];
__device__ float  g_w  [MM * 3];           // sigmoid weight / 3
__device__ double g_sum0[H0], g_ss0[H0], g_sum1[H1], g_ss1[H1];
__device__ float  g_s0[H0], g_t0[H0], g_s1[H1], g_t1[H1];

// ---------------------------------------------------------------------------
// Zero the stats accumulators (must run every graph replay)
// ---------------------------------------------------------------------------
__global__ void zero_stats_kernel() {
    int t = threadIdx.x;
    if (t < H0) { g_sum0[t] = 0.0; g_ss0[t] = 0.0; }
    if (t < H1) { g_sum1[t] = 0.0; g_ss1[t] = 0.0; }
}

// ---------------------------------------------------------------------------
// KNN: for each query point find 3 nearest in xyz2 (stable ties, expanded
// distance formula to match the reference), then compute sigmoid weights.
// grid (NN/256, BB), block 256
// ---------------------------------------------------------------------------
__global__ void knn_kernel(const float* __restrict__ xyz1,
                           const float* __restrict__ xyz2,
                           const float* __restrict__ rel_w,
                           const float* __restrict__ rel_b) {
    __shared__ float4 sh[SS];
    const int b = blockIdx.y;
    const float* x2 = xyz2 + (size_t)b * SS * 3;
    for (int s = threadIdx.x; s < SS; s += 256) {
        float x = x2[s * 3 + 0], y = x2[s * 3 + 1], z = x2[s * 3 + 2];
        sh[s] = make_float4(x, y, z, x * x + y * y + z * z);
    }
    __syncthreads();

    const int n  = blockIdx.x * 256 + threadIdx.x;
    const int gn = b * NN + n;
    const float x1 = xyz1[(size_t)gn * 3 + 0];
    const float y1 = xyz1[(size_t)gn * 3 + 1];
    const float z1 = xyz1[(size_t)gn * 3 + 2];
    const float n1 = x1 * x1 + y1 * y1 + z1 * z1;

    float d0 = 3.4e38f, d1 = 3.4e38f, d2 = 3.4e38f;
    int   i0 = 0, i1 = 0, i2 = 0;

    #pragma unroll 4
    for (int s = 0; s < SS; s++) {
        float4 p = sh[s];
        float dot = x1 * p.x + y1 * p.y + z1 * p.z;
        float d = (n1 + p.w) - 2.0f * dot;
        if (d < d2) {
            if (d < d1) {
                d2 = d1; i2 = i1;
                if (d < d0) { d1 = d0; i1 = i0; d0 = d; i0 = s; }
                else        { d1 = d;  i1 = s; }
            } else { d2 = d; i2 = s; }
        }
    }

    const float rw0 = rel_w[0], rw1 = rel_w[1], rw2 = rel_w[2], rw3 = rel_w[3];
    const float rb  = rel_b[0];
    int   is[3] = { i0, i1, i2 };
    float ds[3] = { d0, d1, d2 };
    #pragma unroll
    for (int k = 0; k < 3; k++) {
        float4 p = sh[is[k]];
        float ox = x1 - p.x, oy = y1 - p.y, oz = z1 - p.z;
        float zlin = ds[k] * rw0 + ox * rw1 + oy * rw2 + oz * rw3 + rb;
        float w = 1.0f / (1.0f + expf(-zlin));
        g_idx[gn * 3 + k] = is[k];
        g_w[gn * 3 + k]   = w * (1.0f / 3.0f);   // fold mean over K
    }
}

// ---------------------------------------------------------------------------
// Interp + concat into g_h = [points1 | interp]   grid MM blocks, 64 threads
// ---------------------------------------------------------------------------
__global__ void interp_kernel(const float* __restrict__ points1,
                              const float* __restrict__ points2) {
    const int gn = blockIdx.x;
    const int b  = gn >> 13;              // gn / NN
    const float* p2b = points2 + (size_t)b * SS * DD;

    const int   j0 = g_idx[gn * 3 + 0], j1 = g_idx[gn * 3 + 1], j2 = g_idx[gn * 3 + 2];
    const float w0 = g_w[gn * 3 + 0],  w1 = g_w[gn * 3 + 1],  w2 = g_w[gn * 3 + 2];

    const float4* r0 = (const float4*)(p2b + (size_t)j0 * DD);
    const float4* r1 = (const float4*)(p2b + (size_t)j1 * DD);
    const float4* r2 = (const float4*)(p2b + (size_t)j2 * DD);
    const float4* q  = (const float4*)(points1 + (size_t)gn * DD);
    float4* h = (float4*)(g_h + (size_t)gn * K0);

    const int c = threadIdx.x;            // 0..63, one float4 each
    h[c] = q[c];
    float4 a = r0[c], bb = r1[c], cc = r2[c];
    float4 o;
    o.x = fmaf(a.x, w0, fmaf(bb.x, w1, cc.x * w2));
    o.y = fmaf(a.y, w0, fmaf(bb.y, w1, cc.y * w2));
    o.z = fmaf(a.z, w0, fmaf(bb.z, w1, cc.z * w2));
    o.w = fmaf(a.w, w0, fmaf(bb.w, w1, cc.w * w2));
    h[64 + c] = o;
}

// ---------------------------------------------------------------------------
// Tiled FP32 GEMM:  C[M,N] = A[M,Kd] @ B[N,Kd]^T + bias
// BM=BN=128, BK=16, 256 threads, 8x8 per thread.
// ACT: apply per-channel affine+ReLU to A on load (fused BN from prev layer).
// ---------------------------------------------------------------------------
template<bool ACT>
__global__ __launch_bounds__(256)
void gemm_kernel(const float* __restrict__ A, const float* __restrict__ Bw,
                 const float* __restrict__ bias,
                 const float* __restrict__ sc, const float* __restrict__ shf,
                 float* __restrict__ C, int N, int Kd) {
    __shared__ float As[16][128];
    __shared__ float Bs[16][128];

    const int tid = threadIdx.x;
    const int bm = blockIdx.y * 128;
    const int bn = blockIdx.x * 128;
    const int lm = tid >> 1;              // 0..127 (row of tile to load)
    const int lk = (tid & 1) * 8;         // 0 or 8 (k-offset to load)
    const int ty = tid >> 4;              // 0..15
    const int tx = tid & 15;              // 0..15

    float acc[8][8];
    #pragma unroll
    for (int i = 0; i < 8; i++)
        #pragma unroll
        for (int j = 0; j < 8; j++) acc[i][j] = 0.0f;

    const float* Ag = A  + (size_t)(bm + lm) * Kd + lk;
    const float* Bg = Bw + (size_t)(bn + lm) * Kd + lk;

    for (int kt = 0; kt < Kd; kt += 16) {
        float4 a0 = *(const float4*)(Ag + kt);
        float4 a1 = *(const float4*)(Ag + kt + 4);
        if (ACT) {
            const float4 s0 = *(const float4*)(sc  + kt + lk);
            const float4 s1 = *(const float4*)(sc  + kt + lk + 4);
            const float4 t0 = *(const float4*)(shf + kt + lk);
            const float4 t1 = *(const float4*)(shf + kt + lk + 4);
            a0.x = fmaxf(0.0f, fmaf(a0.x, s0.x, t0.x));
            a0.y = fmaxf(0.0f, fmaf(a0.y, s0.y, t0.y));
            a0.z = fmaxf(0.0f, fmaf(a0.z, s0.z, t0.z));
            a0.w = fmaxf(0.0f, fmaf(a0.w, s0.w, t0.w));
            a1.x = fmaxf(0.0f, fmaf(a1.x, s1.x, t1.x));
            a1.y = fmaxf(0.0f, fmaf(a1.y, s1.y, t1.y));
            a1.z = fmaxf(0.0f, fmaf(a1.z, s1.z, t1.z));
            a1.w = fmaxf(0.0f, fmaf(a1.w, s1.w, t1.w));
        }
        float4 b0 = *(const float4*)(Bg + kt);
        float4 b1 = *(const float4*)(Bg + kt + 4);

        As[lk + 0][lm] = a0.x;  As[lk + 1][lm] = a0.y;
        As[lk + 2][lm] = a0.z;  As[lk + 3][lm] = a0.w;
        As[lk + 4][lm] = a1.x;  As[lk + 5][lm] = a1.y;
        As[lk + 6][lm] = a1.z;  As[lk + 7][lm] = a1.w;
        Bs[lk + 0][lm] = b0.x;  Bs[lk + 1][lm] = b0.y;
        Bs[lk + 2][lm] = b0.z;  Bs[lk + 3][lm] = b0.w;
        Bs[lk + 4][lm] = b1.x;  Bs[lk + 5][lm] = b1.y;
        Bs[lk + 6][lm] = b1.z;  Bs[lk + 7][lm] = b1.w;
        __syncthreads();

        #pragma unroll
        for (int k = 0; k < 16; k++) {
            float4 av0 = *(const float4*)&As[k][ty * 8];
            float4 av1 = *(const float4*)&As[k][ty * 8 + 4];
            float4 bv0 = *(const float4*)&Bs[k][tx * 8];
            float4 bv1 = *(const float4*)&Bs[k][tx * 8 + 4];
            float ar[8] = { av0.x, av0.y, av0.z, av0.w, av1.x, av1.y, av1.z, av1.w };
            float br[8] = { bv0.x, bv0.y, bv0.z, bv0.w, bv1.x, bv1.y, bv1.z, bv1.w };
            #pragma unroll
            for (int i = 0; i < 8; i++)
                #pragma unroll
                for (int j = 0; j < 8; j++)
                    acc[i][j] = fmaf(ar[i], br[j], acc[i][j]);
        }
        __syncthreads();
    }

    float4 bb0 = *(const float4*)(bias + bn + tx * 8);
    float4 bb1 = *(const float4*)(bias + bn + tx * 8 + 4);
    #pragma unroll
    for (int i = 0; i < 8; i++) {
        size_t row = (size_t)(bm + ty * 8 + i);
        float4 o0, o1;
        o0.x = acc[i][0] + bb0.x;  o0.y = acc[i][1] + bb0.y;
        o0.z = acc[i][2] + bb0.z;  o0.w = acc[i][3] + bb0.w;
        o1.x = acc[i][4] + bb1.x;  o1.y = acc[i][5] + bb1.y;
        o1.z = acc[i][6] + bb1.z;  o1.w = acc[i][7] + bb1.w;
        *(float4*)(C + row * N + bn + tx * 8)     = o0;
        *(float4*)(C + row * N + bn + tx * 8 + 4) = o1;
    }
}

// ---------------------------------------------------------------------------
// Per-channel sum / sumsq (double accumulators, atomic combine)
// block = C threads (one channel each), grid = MM / R
// ---------------------------------------------------------------------------
template<int C, int R>
__global__ void stats_kernel(const float* __restrict__ Y,
                             double* __restrict__ Sum, double* __restrict__ Ss) {
    const int c = threadIdx.x;
    const float* p = Y + (size_t)blockIdx.x * R * C + c;
    double s = 0.0, ss = 0.0;
    #pragma unroll 4
    for (int r = 0; r < R; r++) {
        float v = p[(size_t)r * C];
        s  += (double)v;
        ss += (double)v * (double)v;
    }
    atomicAdd(&Sum[c], s);
    atomicAdd(&Ss[c],  ss);
}

// mean/var -> per-channel scale & shift for fused BN+ReLU
__global__ void finalize_kernel(const double* __restrict__ Sum,
                                const double* __restrict__ Ss,
                                const float* __restrict__ gamma,
                                const float* __restrict__ beta,
                                float* __restrict__ sc, float* __restrict__ shf,
                                int C) {
    int c = threadIdx.x;
    if (c < C) {
        double mean = Sum[c] * (1.0 / (double)MM);
        double var  = Ss[c]  * (1.0 / (double)MM) - mean * mean;
        float s = gamma[c] * rsqrtf((float)var + BNEPS);
        sc[c]  = s;
        shf[c] = beta[c] - (float)mean * s;
    }
}

// final in-place BN + ReLU on d_out (layer 1), float4-vectorized
__global__ void act_kernel(float* __restrict__ Y,
                           const float* __restrict__ sc,
                           const float* __restrict__ shf) {
    int i = blockIdx.x * blockDim.x + threadIdx.x;      // float4 index
    float4 v = ((float4*)Y)[i];
    const float4 s4 = ((const float4*)sc)[i & 31];      // H1/4 = 32
    const float4 t4 = ((const float4*)shf)[i & 31];
    v.x = fmaxf(0.0f, fmaf(v.x, s4.x, t4.x));
    v.y = fmaxf(0.0f, fmaf(v.y, s4.y, t4.y));
    v.z = fmaxf(0.0f, fmaf(v.z, s4.z, t4.z));
    v.w = fmaxf(0.0f, fmaf(v.w, s4.w, t4.w));
    ((float4*)Y)[i] = v;
}

// ---------------------------------------------------------------------------
// Launch sequence
// ---------------------------------------------------------------------------
extern "C" void kernel_launch(void* const* d_in, const int* in_sizes, int n_in,
                              void* d_out, int out_size) {
    const float* xyz1    = (const float*)d_in[0];
    const float* xyz2    = (const float*)d_in[1];
    const float* points1 = (const float*)d_in[2];
    const float* points2 = (const float*)d_in[3];
    const float* rel_w   = (const float*)d_in[4];
    const float* rel_b   = (const float*)d_in[5];
    const float* W0      = (const float*)d_in[6];
    const float* b0      = (const float*)d_in[7];
    const float* g0      = (const float*)d_in[8];
    const float* be0     = (const float*)d_in[9];
    const float* W1      = (const float*)d_in[10];
    const float* b1      = (const float*)d_in[11];
    const float* g1      = (const float*)d_in[12];
    const float* be1     = (const float*)d_in[13];
    float* out = (float*)d_out;

    float *p_h, *p_y0, *p_s0, *p_t0, *p_s1, *p_t1;
    double *p_sum0, *p_ss0, *p_sum1, *p_ss1;
    cudaGetSymbolAddress((void**)&p_h,    g_h);
    cudaGetSymbolAddress((void**)&p_y0,   g_y0);
    cudaGetSymbolAddress((void**)&p_s0,   g_s0);
    cudaGetSymbolAddress((void**)&p_t0,   g_t0);
    cudaGetSymbolAddress((void**)&p_s1,   g_s1);
    cudaGetSymbolAddress((void**)&p_t1,   g_t1);
    cudaGetSymbolAddress((void**)&p_sum0, g_sum0);
    cudaGetSymbolAddress((void**)&p_ss0,  g_ss0);
    cudaGetSymbolAddress((void**)&p_sum1, g_sum1);
    cudaGetSymbolAddress((void**)&p_ss1,  g_ss1);

    zero_stats_kernel<<<1, 256>>>();
    knn_kernel<<<dim3(NN / 256, BB), 256>>>(xyz1, xyz2, rel_w, rel_b);
    interp_kernel<<<MM, 64>>>(points1, points2);

    // layer 0: h[M,512] @ W0[256,512]^T + b0 -> y0
    gemm_kernel<false><<<dim3(H0 / 128, MM / 128), 256>>>(
        p_h, W0, b0, nullptr, nullptr, p_y0, H0, K0);
    stats_kernel<H0, 256><<<MM / 256, H0>>>(p_y0, p_sum0, p_ss0);
    finalize_kernel<<<1, H0>>>(p_sum0, p_ss0, g0, be0, p_s0, p_t0, H0);

    // layer 1: act(y0) @ W1[128,256]^T + b1 -> out (pre-BN)
    gemm_kernel<true><<<dim3(H1 / 128, MM / 128), 256>>>(
        p_y0, W1, b1, p_s0, p_t0, out, H1, H0);
    stats_kernel<H1, 512><<<MM / 512, H1>>>(out, p_sum1, p_ss1);
    finalize_kernel<<<1, H1>>>(p_sum1, p_ss1, g1, be1, p_s1, p_t1, H1);

    // final BN + ReLU in place
    act_kernel<<<(MM * H1 / 4) / 256, 256>>>(out, p_s1, p_t1);
}

// round 3
// speedup vs baseline: 1.6168x; 1.6168x over previous
#include <cuda_runtime.h>
#include <math.h>
#include <stdint.h>

// Problem constants
#define BB   8
#define NN   8192
#define SS   2048
#define DD   256
#define MM   65536      // BB*NN
#define H0   256
#define H1   128
#define K0   512        // 2*DD
#define BNEPS 1e-5f

// ---------------------------------------------------------------------------
// Scratch
// ---------------------------------------------------------------------------
__device__ float  g_h  [(size_t)MM * K0];   // concat(points1, interp)  [M, 512]
__device__ float  g_y0 [(size_t)MM * H0];   // layer0 pre-BN output     [M, 256]
__device__ float  g_act[(size_t)MM * H0];   // relu(bn(y0))             [M, 256]
__device__ int    g_idx[MM * 3];
__device__ float  g_w  [MM * 3];
__device__ double g_sum0[H0], g_ss0[H0], g_sum1[H1], g_ss1[H1];
__device__ float  g_s0[H0], g_t0[H0], g_s1[H1], g_t1[H1];

// ---------------------------------------------------------------------------
// Portable PTX helpers (NO sm_103a-only instructions — toolchain targets sm_103)
// ---------------------------------------------------------------------------
__device__ __forceinline__ uint32_t smem_u32(const void* p) {
    uint32_t a;
    asm("{ .reg .u64 t; cvta.to.shared.u64 t, %1; cvt.u32.u64 %0, t; }" : "=r"(a) : "l"(p));
    return a;
}

#define CP_ASYNC16(dst, src) \
    asm volatile("cp.async.cg.shared.global [%0], [%1], 16;" :: "r"(dst), "l"(src) : "memory")
#define CP_COMMIT() asm volatile("cp.async.commit_group;" ::: "memory")
#define CP_WAIT(n)  asm volatile("cp.async.wait_group %0;" :: "n"(n) : "memory")

__device__ __forceinline__ uint32_t f2tf32(float x) {
    uint32_t r;
    asm("cvt.rna.tf32.f32 %0, %1;" : "=r"(r) : "f"(x));
    return r;
}

__device__ __forceinline__ void mma_tf32_16x8x8(float* c, const uint32_t* a,
                                                const uint32_t* b) {
    asm volatile(
        "mma.sync.aligned.m16n8k8.row.col.f32.tf32.tf32.f32 "
        "{%0,%1,%2,%3}, {%4,%5,%6,%7}, {%8,%9}, {%0,%1,%2,%3};"
        : "+f"(c[0]), "+f"(c[1]), "+f"(c[2]), "+f"(c[3])
        : "r"(a[0]), "r"(a[1]), "r"(a[2]), "r"(a[3]), "r"(b[0]), "r"(b[1]));
}

// ---------------------------------------------------------------------------
// Misc small kernels
// ---------------------------------------------------------------------------
__global__ void zero_stats_kernel() {
    int t = threadIdx.x;
    if (t < H0) { g_sum0[t] = 0.0; g_ss0[t] = 0.0; }
    if (t < H1) { g_sum1[t] = 0.0; g_ss1[t] = 0.0; }
}

__global__ void knn_kernel(const float* __restrict__ xyz1,
                           const float* __restrict__ xyz2,
                           const float* __restrict__ rel_w,
                           const float* __restrict__ rel_b) {
    __shared__ float4 sh[SS];
    const int b = blockIdx.y;
    const float* x2 = xyz2 + (size_t)b * SS * 3;
    for (int s = threadIdx.x; s < SS; s += 256) {
        float x = x2[s * 3 + 0], y = x2[s * 3 + 1], z = x2[s * 3 + 2];
        sh[s] = make_float4(x, y, z, x * x + y * y + z * z);
    }
    __syncthreads();

    const int n  = blockIdx.x * 256 + threadIdx.x;
    const int gn = b * NN + n;
    const float x1 = xyz1[(size_t)gn * 3 + 0];
    const float y1 = xyz1[(size_t)gn * 3 + 1];
    const float z1 = xyz1[(size_t)gn * 3 + 2];
    const float n1 = x1 * x1 + y1 * y1 + z1 * z1;

    float d0 = 3.4e38f, d1 = 3.4e38f, d2 = 3.4e38f;
    int   i0 = 0, i1 = 0, i2 = 0;

    #pragma unroll 4
    for (int s = 0; s < SS; s++) {
        float4 p = sh[s];
        float dot = x1 * p.x + y1 * p.y + z1 * p.z;
        float d = (n1 + p.w) - 2.0f * dot;
        if (d < d2) {
            if (d < d1) {
                d2 = d1; i2 = i1;
                if (d < d0) { d1 = d0; i1 = i0; d0 = d; i0 = s; }
                else        { d1 = d;  i1 = s; }
            } else { d2 = d; i2 = s; }
        }
    }

    const float rw0 = rel_w[0], rw1 = rel_w[1], rw2 = rel_w[2], rw3 = rel_w[3];
    const float rb  = rel_b[0];
    int   is[3] = { i0, i1, i2 };
    float ds[3] = { d0, d1, d2 };
    #pragma unroll
    for (int k = 0; k < 3; k++) {
        float4 p = sh[is[k]];
        float ox = x1 - p.x, oy = y1 - p.y, oz = z1 - p.z;
        float zlin = ds[k] * rw0 + ox * rw1 + oy * rw2 + oz * rw3 + rb;
        float w = 1.0f / (1.0f + expf(-zlin));
        g_idx[gn * 3 + k] = is[k];
        g_w[gn * 3 + k]   = w * (1.0f / 3.0f);
    }
}

__global__ void interp_kernel(const float* __restrict__ points1,
                              const float* __restrict__ points2) {
    const int gn = blockIdx.x;
    const int b  = gn >> 13;
    const float* p2b = points2 + (size_t)b * SS * DD;

    const int   j0 = g_idx[gn * 3 + 0], j1 = g_idx[gn * 3 + 1], j2 = g_idx[gn * 3 + 2];
    const float w0 = g_w[gn * 3 + 0],  w1 = g_w[gn * 3 + 1],  w2 = g_w[gn * 3 + 2];

    const float4* r0 = (const float4*)(p2b + (size_t)j0 * DD);
    const float4* r1 = (const float4*)(p2b + (size_t)j1 * DD);
    const float4* r2 = (const float4*)(p2b + (size_t)j2 * DD);
    const float4* q  = (const float4*)(points1 + (size_t)gn * DD);
    float4* h = (float4*)(g_h + (size_t)gn * K0);

    const int c = threadIdx.x;            // 0..63
    h[c] = q[c];
    float4 a = r0[c], bb = r1[c], cc = r2[c];
    float4 o;
    o.x = fmaf(a.x, w0, fmaf(bb.x, w1, cc.x * w2));
    o.y = fmaf(a.y, w0, fmaf(bb.y, w1, cc.y * w2));
    o.z = fmaf(a.z, w0, fmaf(bb.z, w1, cc.z * w2));
    o.w = fmaf(a.w, w0, fmaf(bb.w, w1, cc.w * w2));
    h[64 + c] = o;
}

// ---------------------------------------------------------------------------
// tf32 mma.sync GEMM:  C[M, NT] = A[M, KT] @ B[NT, KT]^T + bias
// Block tile 128x128, BK=32, double-buffered cp.async. 8 warps (4M x 2N),
// warp tile 32x64 via m16n8k8 tf32 mma (2 m-tiles x 8 n-tiles).
// Smem rows padded to 36 floats: frag-load banks = 4g+tg -> conflict-free.
// ---------------------------------------------------------------------------
template<int NT, int KT>
__global__ __launch_bounds__(256)
void mma_gemm_kernel(const float* __restrict__ A, const float* __restrict__ Bw,
                     const float* __restrict__ bias, float* __restrict__ C) {
    constexpr int NC    = KT / 32;        // BK=32 chunks
    constexpr int LDT   = 36;             // padded row stride (floats), 144B
    constexpr int STAGE = 2 * 128 * LDT;  // floats per stage (A then B)

    extern __shared__ float sm[];
    const uint32_t smb = smem_u32(sm);

    const int tid    = threadIdx.x;
    const int wid    = tid >> 5;
    const int lane   = tid & 31;
    const int g      = lane >> 2;         // 0..7
    const int tg     = lane & 3;          // 0..3
    const int warp_m = wid >> 1;          // 0..3
    const int warp_n = wid & 1;           // 0..1
    const size_t bm  = (size_t)blockIdx.y * 128;
    const size_t bn  = (size_t)blockIdx.x * 128;

    float acc[2][8][4];
    #pragma unroll
    for (int mt = 0; mt < 2; mt++)
        #pragma unroll
        for (int nt = 0; nt < 8; nt++)
            #pragma unroll
            for (int i = 0; i < 4; i++) acc[mt][nt][i] = 0.0f;

    // load one BK=32 stage: A[128][32] and B[128][32], 16B per cp.async
    auto load_stage = [&](int kt, int s) {
        const float* Ag = A + bm * KT + kt * 32;
        const float* Bg = Bw + bn * KT + kt * 32;
        const uint32_t base = smb + (uint32_t)(s * STAGE) * 4u;
        #pragma unroll
        for (int i = 0; i < 4; i++) {
            int id = i * 256 + tid;
            int r = id >> 3, kk = (id & 7) * 4;
            CP_ASYNC16(base + (r * LDT + kk) * 4, Ag + (size_t)r * KT + kk);
        }
        #pragma unroll
        for (int i = 0; i < 4; i++) {
            int id = i * 256 + tid;
            int r = id >> 3, kk = (id & 7) * 4;
            CP_ASYNC16(base + (128 * LDT + r * LDT + kk) * 4, Bg + (size_t)r * KT + kk);
        }
        CP_COMMIT();
    };

    load_stage(0, 0);

    for (int kt = 0; kt < NC; kt++) {
        if (kt + 1 < NC) {
            load_stage(kt + 1, (kt + 1) & 1);
            CP_WAIT(1);
        } else {
            CP_WAIT(0);
        }
        __syncthreads();

        const float* as = sm + (kt & 1) * STAGE + (warp_m * 32) * LDT;
        const float* bs = sm + (kt & 1) * STAGE + 128 * LDT + (warp_n * 64) * LDT;

        #pragma unroll
        for (int kc = 0; kc < 4; kc++) {
            uint32_t a[2][4];
            #pragma unroll
            for (int mt = 0; mt < 2; mt++) {
                int base = (mt * 16 + g) * LDT + kc * 8 + tg;
                a[mt][0] = f2tf32(as[base]);
                a[mt][1] = f2tf32(as[base + 8 * LDT]);
                a[mt][2] = f2tf32(as[base + 4]);
                a[mt][3] = f2tf32(as[base + 8 * LDT + 4]);
            }
            #pragma unroll
            for (int nt = 0; nt < 8; nt++) {
                uint32_t b[2];
                int bb = (nt * 8 + g) * LDT + kc * 8 + tg;
                b[0] = f2tf32(bs[bb]);
                b[1] = f2tf32(bs[bb + 4]);
                mma_tf32_16x8x8(acc[0][nt], a[0], b);
                mma_tf32_16x8x8(acc[1][nt], a[1], b);
            }
        }
        __syncthreads();
    }

    // epilogue: + bias, direct float2 stores
    #pragma unroll
    for (int mt = 0; mt < 2; mt++) {
        #pragma unroll
        for (int nt = 0; nt < 8; nt++) {
            size_t col = bn + warp_n * 64 + nt * 8 + 2 * tg;
            float bi0 = __ldg(&bias[col]), bi1 = __ldg(&bias[col + 1]);
            size_t r0 = bm + warp_m * 32 + mt * 16 + g;
            float2 v0 = make_float2(acc[mt][nt][0] + bi0, acc[mt][nt][1] + bi1);
            float2 v1 = make_float2(acc[mt][nt][2] + bi0, acc[mt][nt][3] + bi1);
            *(float2*)(C + r0 * NT + col)       = v0;
            *(float2*)(C + (r0 + 8) * NT + col) = v1;
        }
    }
}

// ---------------------------------------------------------------------------
// Stats / BN kernels
// ---------------------------------------------------------------------------
template<int C, int R>
__global__ void stats_kernel(const float* __restrict__ Y,
                             double* __restrict__ Sum, double* __restrict__ Ss) {
    const int c = threadIdx.x;
    const float* p = Y + (size_t)blockIdx.x * R * C + c;
    double s = 0.0, ss = 0.0;
    #pragma unroll 4
    for (int r = 0; r < R; r++) {
        float v = p[(size_t)r * C];
        s  += (double)v;
        ss += (double)v * (double)v;
    }
    atomicAdd(&Sum[c], s);
    atomicAdd(&Ss[c],  ss);
}

__global__ void finalize_kernel(const double* __restrict__ Sum,
                                const double* __restrict__ Ss,
                                const float* __restrict__ gamma,
                                const float* __restrict__ beta,
                                float* __restrict__ sc, float* __restrict__ shf,
                                int C) {
    int c = threadIdx.x;
    if (c < C) {
        double mean = Sum[c] * (1.0 / (double)MM);
        double var  = Ss[c]  * (1.0 / (double)MM) - mean * mean;
        float s = gamma[c] * rsqrtf((float)var + BNEPS);
        sc[c]  = s;
        shf[c] = beta[c] - (float)mean * s;
    }
}

// BN+ReLU for layer 0: g_act = relu(s0 * y0 + t0)
__global__ void act0_kernel(const float* __restrict__ Y, float* __restrict__ O,
                            const float* __restrict__ sc,
                            const float* __restrict__ shf) {
    int i = blockIdx.x * blockDim.x + threadIdx.x;   // float4 index
    float4 v = ((const float4*)Y)[i];
    const float4 s4 = ((const float4*)sc)[i & 63];   // H0/4 = 64
    const float4 t4 = ((const float4*)shf)[i & 63];
    v.x = fmaxf(0.0f, fmaf(v.x, s4.x, t4.x));
    v.y = fmaxf(0.0f, fmaf(v.y, s4.y, t4.y));
    v.z = fmaxf(0.0f, fmaf(v.z, s4.z, t4.z));
    v.w = fmaxf(0.0f, fmaf(v.w, s4.w, t4.w));
    ((float4*)O)[i] = v;
}

// final BN+ReLU in place on d_out (layer 1)
__global__ void act_kernel(float* __restrict__ Y,
                           const float* __restrict__ sc,
                           const float* __restrict__ shf) {
    int i = blockIdx.x * blockDim.x + threadIdx.x;
    float4 v = ((float4*)Y)[i];
    const float4 s4 = ((const float4*)sc)[i & 31];   // H1/4 = 32
    const float4 t4 = ((const float4*)shf)[i & 31];
    v.x = fmaxf(0.0f, fmaf(v.x, s4.x, t4.x));
    v.y = fmaxf(0.0f, fmaf(v.y, s4.y, t4.y));
    v.z = fmaxf(0.0f, fmaf(v.z, s4.z, t4.z));
    v.w = fmaxf(0.0f, fmaf(v.w, s4.w, t4.w));
    ((float4*)Y)[i] = v;
}

// ---------------------------------------------------------------------------
// Launch sequence
// ---------------------------------------------------------------------------
extern "C" void kernel_launch(void* const* d_in, const int* in_sizes, int n_in,
                              void* d_out, int out_size) {
    const float* xyz1    = (const float*)d_in[0];
    const float* xyz2    = (const float*)d_in[1];
    const float* points1 = (const float*)d_in[2];
    const float* points2 = (const float*)d_in[3];
    const float* rel_w   = (const float*)d_in[4];
    const float* rel_b   = (const float*)d_in[5];
    const float* W0      = (const float*)d_in[6];
    const float* b0      = (const float*)d_in[7];
    const float* g0      = (const float*)d_in[8];
    const float* be0     = (const float*)d_in[9];
    const float* W1      = (const float*)d_in[10];
    const float* b1      = (const float*)d_in[11];
    const float* g1      = (const float*)d_in[12];
    const float* be1     = (const float*)d_in[13];
    float* out = (float*)d_out;

    float *p_h, *p_y0, *p_act, *p_s0, *p_t0, *p_s1, *p_t1;
    double *p_sum0, *p_ss0, *p_sum1, *p_ss1;
    cudaGetSymbolAddress((void**)&p_h,    g_h);
    cudaGetSymbolAddress((void**)&p_y0,   g_y0);
    cudaGetSymbolAddress((void**)&p_act,  g_act);
    cudaGetSymbolAddress((void**)&p_s0,   g_s0);
    cudaGetSymbolAddress((void**)&p_t0,   g_t0);
    cudaGetSymbolAddress((void**)&p_s1,   g_s1);
    cudaGetSymbolAddress((void**)&p_t1,   g_t1);
    cudaGetSymbolAddress((void**)&p_sum0, g_sum0);
    cudaGetSymbolAddress((void**)&p_ss0,  g_ss0);
    cudaGetSymbolAddress((void**)&p_sum1, g_sum1);
    cudaGetSymbolAddress((void**)&p_ss1,  g_ss1);

    // dynamic smem: 2 stages x (A 128x36 + B 128x36) floats = 73728 B
    const int smem = 2 * 2 * 128 * 36 * 4;
    cudaFuncSetAttribute(mma_gemm_kernel<H0, K0>,
                         cudaFuncAttributeMaxDynamicSharedMemorySize, smem);
    cudaFuncSetAttribute(mma_gemm_kernel<H1, H0>,
                         cudaFuncAttributeMaxDynamicSharedMemorySize, smem);

    zero_stats_kernel<<<1, 256>>>();
    knn_kernel<<<dim3(NN / 256, BB), 256>>>(xyz1, xyz2, rel_w, rel_b);
    interp_kernel<<<MM, 64>>>(points1, points2);

    // layer 0: h[M,512] @ W0[256,512]^T + b0 -> y0   (tf32 mma.sync)
    mma_gemm_kernel<H0, K0><<<dim3(H0 / 128, MM / 128), 256, smem>>>(p_h, W0, b0, p_y0);
    stats_kernel<H0, 256><<<MM / 256, H0>>>(p_y0, p_sum0, p_ss0);
    finalize_kernel<<<1, H0>>>(p_sum0, p_ss0, g0, be0, p_s0, p_t0, H0);
    act0_kernel<<<(MM * H0 / 4) / 256, 256>>>(p_y0, p_act, p_s0, p_t0);

    // layer 1: act[M,256] @ W1[128,256]^T + b1 -> out (pre-BN)
    mma_gemm_kernel<H1, H0><<<dim3(H1 / 128, MM / 128), 256, smem>>>(p_act, W1, b1, out);
    stats_kernel<H1, 512><<<MM / 512, H1>>>(out, p_sum1, p_ss1);
    finalize_kernel<<<1, H1>>>(p_sum1, p_ss1, g1, be1, p_s1, p_t1, H1);

    act_kernel<<<(MM * H1 / 4) / 256, 256>>>(out, p_s1, p_t1);
}

// round 4
// speedup vs baseline: 1.7325x; 1.0715x over previous
#include <cuda_runtime.h>
#include <math.h>
#include <stdint.h>

// Problem constants
#define BB   8
#define NN   8192
#define SS   2048
#define DD   256
#define MM   65536      // BB*NN
#define H0   256
#define H1   128
#define K0   512        // 2*DD
#define BNEPS 1e-5f

// ---------------------------------------------------------------------------
// Scratch
// ---------------------------------------------------------------------------
__device__ float  g_h  [(size_t)MM * K0];   // concat(points1, interp), tf32 bits
__device__ float  g_y0 [(size_t)MM * H0];   // layer0 pre-BN output (fp32)
__device__ float  g_act[(size_t)MM * H0];   // relu(bn(y0)), tf32 bits
__device__ float  g_w0t[H0 * K0];           // W0 as tf32 bits
__device__ float  g_w1t[H1 * H0];           // W1 as tf32 bits
__device__ int    g_idx[MM * 3];
__device__ float  g_w  [MM * 3];
__device__ double g_sum0[H0], g_ss0[H0], g_sum1[H1], g_ss1[H1];
__device__ float  g_s0[H0], g_t0[H0], g_s1[H1], g_t1[H1];

// ---------------------------------------------------------------------------
// Portable PTX helpers (toolchain targets sm_103 — no arch-accelerated instrs)
// ---------------------------------------------------------------------------
__device__ __forceinline__ uint32_t smem_u32(const void* p) {
    uint32_t a;
    asm("{ .reg .u64 t; cvta.to.shared.u64 t, %1; cvt.u32.u64 %0, t; }" : "=r"(a) : "l"(p));
    return a;
}

#define CP_ASYNC16(dst, src) \
    asm volatile("cp.async.cg.shared.global [%0], [%1], 16;" :: "r"(dst), "l"(src) : "memory")
#define CP_COMMIT() asm volatile("cp.async.commit_group;" ::: "memory")
#define CP_WAIT(n)  asm volatile("cp.async.wait_group %0;" :: "n"(n) : "memory")

__device__ __forceinline__ float f2tf32f(float x) {
    uint32_t r;
    asm("cvt.rna.tf32.f32 %0, %1;" : "=r"(r) : "f"(x));
    return __uint_as_float(r);
}

__device__ __forceinline__ void mma_tf32_16x8x8(float* c, const uint32_t* a,
                                                const uint32_t* b) {
    asm volatile(
        "mma.sync.aligned.m16n8k8.row.col.f32.tf32.tf32.f32 "
        "{%0,%1,%2,%3}, {%4,%5,%6,%7}, {%8,%9}, {%0,%1,%2,%3};"
        : "+f"(c[0]), "+f"(c[1]), "+f"(c[2]), "+f"(c[3])
        : "r"(a[0]), "r"(a[1]), "r"(a[2]), "r"(a[3]), "r"(b[0]), "r"(b[1]));
}

// ---------------------------------------------------------------------------
// Misc small kernels
// ---------------------------------------------------------------------------
__global__ void zero_stats_kernel() {
    int t = threadIdx.x;
    if (t < H0) { g_sum0[t] = 0.0; g_ss0[t] = 0.0; }
    if (t < H1) { g_sum1[t] = 0.0; g_ss1[t] = 0.0; }
}

// convert W0, W1 to tf32 bit patterns
__global__ void convert_w_kernel(const float* __restrict__ W0,
                                 const float* __restrict__ W1) {
    int i = blockIdx.x * blockDim.x + threadIdx.x;
    if (i < H0 * K0) g_w0t[i] = f2tf32f(W0[i]);
    if (i < H1 * H0) g_w1t[i] = f2tf32f(W1[i]);
}

__global__ void knn_kernel(const float* __restrict__ xyz1,
                           const float* __restrict__ xyz2,
                           const float* __restrict__ rel_w,
                           const float* __restrict__ rel_b) {
    __shared__ float4 sh[SS];
    const int b = blockIdx.y;
    const float* x2 = xyz2 + (size_t)b * SS * 3;
    for (int s = threadIdx.x; s < SS; s += 256) {
        float x = x2[s * 3 + 0], y = x2[s * 3 + 1], z = x2[s * 3 + 2];
        sh[s] = make_float4(x, y, z, x * x + y * y + z * z);
    }
    __syncthreads();

    const int n  = blockIdx.x * 256 + threadIdx.x;
    const int gn = b * NN + n;
    const float x1 = xyz1[(size_t)gn * 3 + 0];
    const float y1 = xyz1[(size_t)gn * 3 + 1];
    const float z1 = xyz1[(size_t)gn * 3 + 2];
    const float n1 = x1 * x1 + y1 * y1 + z1 * z1;

    float d0 = 3.4e38f, d1 = 3.4e38f, d2 = 3.4e38f;
    int   i0 = 0, i1 = 0, i2 = 0;

    #pragma unroll 4
    for (int s = 0; s < SS; s++) {
        float4 p = sh[s];
        float dot = x1 * p.x + y1 * p.y + z1 * p.z;
        float d = (n1 + p.w) - 2.0f * dot;
        if (d < d2) {
            if (d < d1) {
                d2 = d1; i2 = i1;
                if (d < d0) { d1 = d0; i1 = i0; d0 = d; i0 = s; }
                else        { d1 = d;  i1 = s; }
            } else { d2 = d; i2 = s; }
        }
    }

    const float rw0 = rel_w[0], rw1 = rel_w[1], rw2 = rel_w[2], rw3 = rel_w[3];
    const float rb  = rel_b[0];
    int   is[3] = { i0, i1, i2 };
    float ds[3] = { d0, d1, d2 };
    #pragma unroll
    for (int k = 0; k < 3; k++) {
        float4 p = sh[is[k]];
        float ox = x1 - p.x, oy = y1 - p.y, oz = z1 - p.z;
        float zlin = ds[k] * rw0 + ox * rw1 + oy * rw2 + oz * rw3 + rb;
        float w = 1.0f / (1.0f + expf(-zlin));
        g_idx[gn * 3 + k] = is[k];
        g_w[gn * 3 + k]   = w * (1.0f / 3.0f);
    }
}

// interp + concat; writes tf32-rounded bit patterns (GEMM0 consumes directly)
// 256 threads, 4 points per block
__global__ void interp_kernel(const float* __restrict__ points1,
                              const float* __restrict__ points2) {
    const int gn = blockIdx.x * 4 + (threadIdx.x >> 6);
    const int c  = threadIdx.x & 63;      // float4 index within row
    const int b  = gn >> 13;
    const float* p2b = points2 + (size_t)b * SS * DD;

    const int   j0 = g_idx[gn * 3 + 0], j1 = g_idx[gn * 3 + 1], j2 = g_idx[gn * 3 + 2];
    const float w0 = g_w[gn * 3 + 0],  w1 = g_w[gn * 3 + 1],  w2 = g_w[gn * 3 + 2];

    const float4* r0 = (const float4*)(p2b + (size_t)j0 * DD);
    const float4* r1 = (const float4*)(p2b + (size_t)j1 * DD);
    const float4* r2 = (const float4*)(p2b + (size_t)j2 * DD);
    const float4* q  = (const float4*)(points1 + (size_t)gn * DD);
    float4* h = (float4*)(g_h + (size_t)gn * K0);

    float4 p1 = q[c];
    p1.x = f2tf32f(p1.x); p1.y = f2tf32f(p1.y);
    p1.z = f2tf32f(p1.z); p1.w = f2tf32f(p1.w);
    h[c] = p1;

    float4 a = r0[c], bb = r1[c], cc = r2[c];
    float4 o;
    o.x = f2tf32f(fmaf(a.x, w0, fmaf(bb.x, w1, cc.x * w2)));
    o.y = f2tf32f(fmaf(a.y, w0, fmaf(bb.y, w1, cc.y * w2)));
    o.z = f2tf32f(fmaf(a.z, w0, fmaf(bb.z, w1, cc.z * w2)));
    o.w = f2tf32f(fmaf(a.w, w0, fmaf(bb.w, w1, cc.w * w2)));
    h[64 + c] = o;
}

// ---------------------------------------------------------------------------
// tf32 mma.sync GEMM:  C[M, NT] = A[M, KT] @ B[NT, KT]^T + bias
// A, B hold pre-rounded tf32 bit patterns; fragment loads are raw uint32.
// Block tile 128x128, BK=32, double-buffered cp.async, 8 warps (4M x 2N).
// ---------------------------------------------------------------------------
template<int NT, int KT>
__global__ __launch_bounds__(256)
void mma_gemm_kernel(const float* __restrict__ A, const float* __restrict__ Bw,
                     const float* __restrict__ bias, float* __restrict__ C) {
    constexpr int NC    = KT / 32;        // BK=32 chunks
    constexpr int LDT   = 36;             // padded row stride (floats)
    constexpr int STAGE = 2 * 128 * LDT;  // floats per stage (A then B)

    extern __shared__ float sm[];
    const uint32_t smb = smem_u32(sm);

    const int tid    = threadIdx.x;
    const int wid    = tid >> 5;
    const int lane   = tid & 31;
    const int g      = lane >> 2;         // 0..7
    const int tg     = lane & 3;          // 0..3
    const int warp_m = wid >> 1;          // 0..3
    const int warp_n = wid & 1;           // 0..1
    const size_t bm  = (size_t)blockIdx.y * 128;
    const size_t bn  = (size_t)blockIdx.x * 128;

    float acc[2][8][4];
    #pragma unroll
    for (int mt = 0; mt < 2; mt++)
        #pragma unroll
        for (int nt = 0; nt < 8; nt++)
            #pragma unroll
            for (int i = 0; i < 4; i++) acc[mt][nt][i] = 0.0f;

    auto load_stage = [&](int kt, int s) {
        const float* Ag = A + bm * KT + kt * 32;
        const float* Bg = Bw + bn * KT + kt * 32;
        const uint32_t base = smb + (uint32_t)(s * STAGE) * 4u;
        #pragma unroll
        for (int i = 0; i < 4; i++) {
            int id = i * 256 + tid;
            int r = id >> 3, kk = (id & 7) * 4;
            CP_ASYNC16(base + (r * LDT + kk) * 4, Ag + (size_t)r * KT + kk);
        }
        #pragma unroll
        for (int i = 0; i < 4; i++) {
            int id = i * 256 + tid;
            int r = id >> 3, kk = (id & 7) * 4;
            CP_ASYNC16(base + (128 * LDT + r * LDT + kk) * 4, Bg + (size_t)r * KT + kk);
        }
        CP_COMMIT();
    };

    load_stage(0, 0);

    for (int kt = 0; kt < NC; kt++) {
        if (kt + 1 < NC) {
            load_stage(kt + 1, (kt + 1) & 1);
            CP_WAIT(1);
        } else {
            CP_WAIT(0);
        }
        __syncthreads();

        const uint32_t* as = (const uint32_t*)sm + (kt & 1) * STAGE + (warp_m * 32) * LDT;
        const uint32_t* bs = (const uint32_t*)sm + (kt & 1) * STAGE + 128 * LDT
                           + (warp_n * 64) * LDT;

        #pragma unroll
        for (int kc = 0; kc < 4; kc++) {
            uint32_t a[2][4];
            #pragma unroll
            for (int mt = 0; mt < 2; mt++) {
                int base = (mt * 16 + g) * LDT + kc * 8 + tg;
                a[mt][0] = as[base];
                a[mt][1] = as[base + 8 * LDT];
                a[mt][2] = as[base + 4];
                a[mt][3] = as[base + 8 * LDT + 4];
            }
            #pragma unroll
            for (int nt = 0; nt < 8; nt++) {
                uint32_t b[2];
                int bb = (nt * 8 + g) * LDT + kc * 8 + tg;
                b[0] = bs[bb];
                b[1] = bs[bb + 4];
                mma_tf32_16x8x8(acc[0][nt], a[0], b);
                mma_tf32_16x8x8(acc[1][nt], a[1], b);
            }
        }
        __syncthreads();
    }

    // epilogue: + bias, direct float2 stores
    #pragma unroll
    for (int mt = 0; mt < 2; mt++) {
        #pragma unroll
        for (int nt = 0; nt < 8; nt++) {
            size_t col = bn + warp_n * 64 + nt * 8 + 2 * tg;
            float bi0 = __ldg(&bias[col]), bi1 = __ldg(&bias[col + 1]);
            size_t r0 = bm + warp_m * 32 + mt * 16 + g;
            float2 v0 = make_float2(acc[mt][nt][0] + bi0, acc[mt][nt][1] + bi1);
            float2 v1 = make_float2(acc[mt][nt][2] + bi0, acc[mt][nt][3] + bi1);
            *(float2*)(C + r0 * NT + col)       = v0;
            *(float2*)(C + (r0 + 8) * NT + col) = v1;
        }
    }
}

// ---------------------------------------------------------------------------
// Stats / BN kernels
// ---------------------------------------------------------------------------
template<int C, int R>
__global__ void stats_kernel(const float* __restrict__ Y,
                             double* __restrict__ Sum, double* __restrict__ Ss) {
    const int c = threadIdx.x;
    const float* p = Y + (size_t)blockIdx.x * R * C + c;
    double s = 0.0, ss = 0.0;
    #pragma unroll 4
    for (int r = 0; r < R; r++) {
        float v = p[(size_t)r * C];
        s  += (double)v;
        ss += (double)v * (double)v;
    }
    atomicAdd(&Sum[c], s);
    atomicAdd(&Ss[c],  ss);
}

__global__ void finalize_kernel(const double* __restrict__ Sum,
                                const double* __restrict__ Ss,
                                const float* __restrict__ gamma,
                                const float* __restrict__ beta,
                                float* __restrict__ sc, float* __restrict__ shf,
                                int C) {
    int c = threadIdx.x;
    if (c < C) {
        double mean = Sum[c] * (1.0 / (double)MM);
        double var  = Ss[c]  * (1.0 / (double)MM) - mean * mean;
        float s = gamma[c] * rsqrtf((float)var + BNEPS);
        sc[c]  = s;
        shf[c] = beta[c] - (float)mean * s;
    }
}

// BN+ReLU for layer 0; writes tf32-rounded bits (GEMM1 A operand)
__global__ void act0_kernel(const float* __restrict__ Y, float* __restrict__ O,
                            const float* __restrict__ sc,
                            const float* __restrict__ shf) {
    int i = blockIdx.x * blockDim.x + threadIdx.x;   // float4 index
    float4 v = ((const float4*)Y)[i];
    const float4 s4 = ((const float4*)sc)[i & 63];   // H0/4 = 64
    const float4 t4 = ((const float4*)shf)[i & 63];
    v.x = f2tf32f(fmaxf(0.0f, fmaf(v.x, s4.x, t4.x)));
    v.y = f2tf32f(fmaxf(0.0f, fmaf(v.y, s4.y, t4.y)));
    v.z = f2tf32f(fmaxf(0.0f, fmaf(v.z, s4.z, t4.z)));
    v.w = f2tf32f(fmaxf(0.0f, fmaf(v.w, s4.w, t4.w)));
    ((float4*)O)[i] = v;
}

// final BN+ReLU in place on d_out (layer 1)
__global__ void act_kernel(float* __restrict__ Y,
                           const float* __restrict__ sc,
                           const float* __restrict__ shf) {
    int i = blockIdx.x * blockDim.x + threadIdx.x;
    float4 v = ((float4*)Y)[i];
    const float4 s4 = ((const float4*)sc)[i & 31];   // H1/4 = 32
    const float4 t4 = ((const float4*)shf)[i & 31];
    v.x = fmaxf(0.0f, fmaf(v.x, s4.x, t4.x));
    v.y = fmaxf(0.0f, fmaf(v.y, s4.y, t4.y));
    v.z = fmaxf(0.0f, fmaf(v.z, s4.z, t4.z));
    v.w = fmaxf(0.0f, fmaf(v.w, s4.w, t4.w));
    ((float4*)Y)[i] = v;
}

// ---------------------------------------------------------------------------
// Launch sequence
// ---------------------------------------------------------------------------
extern "C" void kernel_launch(void* const* d_in, const int* in_sizes, int n_in,
                              void* d_out, int out_size) {
    const float* xyz1    = (const float*)d_in[0];
    const float* xyz2    = (const float*)d_in[1];
    const float* points1 = (const float*)d_in[2];
    const float* points2 = (const float*)d_in[3];
    const float* rel_w   = (const float*)d_in[4];
    const float* rel_b   = (const float*)d_in[5];
    const float* W0      = (const float*)d_in[6];
    const float* b0      = (const float*)d_in[7];
    const float* g0      = (const float*)d_in[8];
    const float* be0     = (const float*)d_in[9];
    const float* W1      = (const float*)d_in[10];
    const float* b1      = (const float*)d_in[11];
    const float* g1      = (const float*)d_in[12];
    const float* be1     = (const float*)d_in[13];
    float* out = (float*)d_out;

    float *p_h, *p_y0, *p_act, *p_w0t, *p_w1t, *p_s0, *p_t0, *p_s1, *p_t1;
    double *p_sum0, *p_ss0, *p_sum1, *p_ss1;
    cudaGetSymbolAddress((void**)&p_h,    g_h);
    cudaGetSymbolAddress((void**)&p_y0,   g_y0);
    cudaGetSymbolAddress((void**)&p_act,  g_act);
    cudaGetSymbolAddress((void**)&p_w0t,  g_w0t);
    cudaGetSymbolAddress((void**)&p_w1t,  g_w1t);
    cudaGetSymbolAddress((void**)&p_s0,   g_s0);
    cudaGetSymbolAddress((void**)&p_t0,   g_t0);
    cudaGetSymbolAddress((void**)&p_s1,   g_s1);
    cudaGetSymbolAddress((void**)&p_t1,   g_t1);
    cudaGetSymbolAddress((void**)&p_sum0, g_sum0);
    cudaGetSymbolAddress((void**)&p_ss0,  g_ss0);
    cudaGetSymbolAddress((void**)&p_sum1, g_sum1);
    cudaGetSymbolAddress((void**)&p_ss1,  g_ss1);

    // dynamic smem: 2 stages x (A 128x36 + B 128x36) floats = 73728 B
    const int smem = 2 * 2 * 128 * 36 * 4;
    cudaFuncSetAttribute(mma_gemm_kernel<H0, K0>,
                         cudaFuncAttributeMaxDynamicSharedMemorySize, smem);
    cudaFuncSetAttribute(mma_gemm_kernel<H1, H0>,
                         cudaFuncAttributeMaxDynamicSharedMemorySize, smem);

    zero_stats_kernel<<<1, 256>>>();
    convert_w_kernel<<<(H0 * K0 + 255) / 256, 256>>>(W0, W1);
    knn_kernel<<<dim3(NN / 256, BB), 256>>>(xyz1, xyz2, rel_w, rel_b);
    interp_kernel<<<MM / 4, 256>>>(points1, points2);

    // layer 0: h[M,512] @ W0[256,512]^T + b0 -> y0   (tf32 mma.sync)
    mma_gemm_kernel<H0, K0><<<dim3(H0 / 128, MM / 128), 256, smem>>>(p_h, p_w0t, b0, p_y0);
    stats_kernel<H0, 256><<<MM / 256, H0>>>(p_y0, p_sum0, p_ss0);
    finalize_kernel<<<1, H0>>>(p_sum0, p_ss0, g0, be0, p_s0, p_t0, H0);
    act0_kernel<<<(MM * H0 / 4) / 256, 256>>>(p_y0, p_act, p_s0, p_t0);

    // layer 1: act[M,256] @ W1[128,256]^T + b1 -> out (pre-BN)
    mma_gemm_kernel<H1, H0><<<dim3(H1 / 128, MM / 128), 256, smem>>>(p_act, p_w1t, b1, out);
    stats_kernel<H1, 512><<<MM / 512, H1>>>(out, p_sum1, p_ss1);
    finalize_kernel<<<1, H1>>>(p_sum1, p_ss1, g1, be1, p_s1, p_t1, H1);

    act_kernel<<<(MM * H1 / 4) / 256, 256>>>(out, p_s1, p_t1);
}

// round 6
// speedup vs baseline: 1.7565x; 1.0138x over previous
#include <cuda_runtime.h>
#include <math.h>
#include <stdint.h>

// Problem constants
#define BB   8
#define NN   8192
#define SS   2048
#define DD   256
#define MM   65536      // BB*NN
#define H0   256
#define H1   128
#define K0   512        // 2*DD
#define BNEPS 1e-5f

// ---------------------------------------------------------------------------
// Scratch
// ---------------------------------------------------------------------------
__device__ float  g_h  [(size_t)MM * K0];   // concat(points1, interp), tf32 bits
__device__ float  g_y0 [(size_t)MM * H0];   // layer0 pre-BN output (fp32)
__device__ float  g_w0t[H0 * K0];           // W0 as tf32 bits
__device__ float  g_w1t[H1 * H0];           // W1 as tf32 bits
__device__ int    g_idx[MM * 3];
__device__ float  g_w  [MM * 3];
__device__ double g_sum0[H0], g_ss0[H0], g_sum1[H1], g_ss1[H1];
__device__ float  g_s0[H0], g_t0[H0], g_s1[H1], g_t1[H1];

// ---------------------------------------------------------------------------
// Portable PTX helpers (toolchain targets sm_103 — no arch-accelerated instrs)
// ---------------------------------------------------------------------------
__device__ __forceinline__ uint32_t smem_u32(const void* p) {
    uint32_t a;
    asm("{ .reg .u64 t; cvta.to.shared.u64 t, %1; cvt.u32.u64 %0, t; }" : "=r"(a) : "l"(p));
    return a;
}

#define CP_ASYNC16(dst, src) \
    asm volatile("cp.async.cg.shared.global [%0], [%1], 16;" :: "r"(dst), "l"(src) : "memory")
#define CP_COMMIT() asm volatile("cp.async.commit_group;" ::: "memory")
#define CP_WAIT(n)  asm volatile("cp.async.wait_group %0;" :: "n"(n) : "memory")

__device__ __forceinline__ float f2tf32f(float x) {
    uint32_t r;
    asm("cvt.rna.tf32.f32 %0, %1;" : "=r"(r) : "f"(x));
    return __uint_as_float(r);
}

__device__ __forceinline__ void mma_tf32_16x8x8(float* c, const uint32_t* a,
                                                const uint32_t* b) {
    asm volatile(
        "mma.sync.aligned.m16n8k8.row.col.f32.tf32.tf32.f32 "
        "{%0,%1,%2,%3}, {%4,%5,%6,%7}, {%8,%9}, {%0,%1,%2,%3};"
        : "+f"(c[0]), "+f"(c[1]), "+f"(c[2]), "+f"(c[3])
        : "r"(a[0]), "r"(a[1]), "r"(a[2]), "r"(a[3]), "r"(b[0]), "r"(b[1]));
}

// ---------------------------------------------------------------------------
// Misc small kernels
// ---------------------------------------------------------------------------
__global__ void zero_stats_kernel() {
    int t = threadIdx.x;
    if (t < H0) { g_sum0[t] = 0.0; g_ss0[t] = 0.0; }
    if (t < H1) { g_sum1[t] = 0.0; g_ss1[t] = 0.0; }
}

// convert W0, W1 to tf32 bit patterns
__global__ void convert_w_kernel(const float* __restrict__ W0,
                                 const float* __restrict__ W1) {
    int i = blockIdx.x * blockDim.x + threadIdx.x;
    if (i < H0 * K0) g_w0t[i] = f2tf32f(W0[i]);
    if (i < H1 * H0) g_w1t[i] = f2tf32f(W1[i]);
}

__global__ void knn_kernel(const float* __restrict__ xyz1,
                           const float* __restrict__ xyz2,
                           const float* __restrict__ rel_w,
                           const float* __restrict__ rel_b) {
    __shared__ float4 sh[SS];
    const int b = blockIdx.y;
    const float* x2 = xyz2 + (size_t)b * SS * 3;
    for (int s = threadIdx.x; s < SS; s += 256) {
        float x = x2[s * 3 + 0], y = x2[s * 3 + 1], z = x2[s * 3 + 2];
        sh[s] = make_float4(x, y, z, x * x + y * y + z * z);
    }
    __syncthreads();

    const int n  = blockIdx.x * 256 + threadIdx.x;
    const int gn = b * NN + n;
    const float x1 = xyz1[(size_t)gn * 3 + 0];
    const float y1 = xyz1[(size_t)gn * 3 + 1];
    const float z1 = xyz1[(size_t)gn * 3 + 2];
    const float n1 = x1 * x1 + y1 * y1 + z1 * z1;

    float d0 = 3.4e38f, d1 = 3.4e38f, d2 = 3.4e38f;
    int   i0 = 0, i1 = 0, i2 = 0;

    #pragma unroll 4
    for (int s = 0; s < SS; s++) {
        float4 p = sh[s];
        float dot = x1 * p.x + y1 * p.y + z1 * p.z;
        float d = (n1 + p.w) - 2.0f * dot;
        if (d < d2) {
            if (d < d1) {
                d2 = d1; i2 = i1;
                if (d < d0) { d1 = d0; i1 = i0; d0 = d; i0 = s; }
                else        { d1 = d;  i1 = s; }
            } else { d2 = d; i2 = s; }
        }
    }

    const float rw0 = rel_w[0], rw1 = rel_w[1], rw2 = rel_w[2], rw3 = rel_w[3];
    const float rb  = rel_b[0];
    int   is[3] = { i0, i1, i2 };
    float ds[3] = { d0, d1, d2 };
    #pragma unroll
    for (int k = 0; k < 3; k++) {
        float4 p = sh[is[k]];
        float ox = x1 - p.x, oy = y1 - p.y, oz = z1 - p.z;
        float zlin = ds[k] * rw0 + ox * rw1 + oy * rw2 + oz * rw3 + rb;
        float w = 1.0f / (1.0f + expf(-zlin));
        g_idx[gn * 3 + k] = is[k];
        g_w[gn * 3 + k]   = w * (1.0f / 3.0f);
    }
}

// interp + concat; writes tf32-rounded bit patterns (GEMM0 consumes directly)
__global__ void interp_kernel(const float* __restrict__ points1,
                              const float* __restrict__ points2) {
    const int gn = blockIdx.x * 4 + (threadIdx.x >> 6);
    const int c  = threadIdx.x & 63;      // float4 index within row
    const int b  = gn >> 13;
    const float* p2b = points2 + (size_t)b * SS * DD;

    const int   j0 = g_idx[gn * 3 + 0], j1 = g_idx[gn * 3 + 1], j2 = g_idx[gn * 3 + 2];
    const float w0 = g_w[gn * 3 + 0],  w1 = g_w[gn * 3 + 1],  w2 = g_w[gn * 3 + 2];

    const float4* r0 = (const float4*)(p2b + (size_t)j0 * DD);
    const float4* r1 = (const float4*)(p2b + (size_t)j1 * DD);
    const float4* r2 = (const float4*)(p2b + (size_t)j2 * DD);
    const float4* q  = (const float4*)(points1 + (size_t)gn * DD);
    float4* h = (float4*)(g_h + (size_t)gn * K0);

    float4 p1 = q[c];
    p1.x = f2tf32f(p1.x); p1.y = f2tf32f(p1.y);
    p1.z = f2tf32f(p1.z); p1.w = f2tf32f(p1.w);
    h[c] = p1;

    float4 a = r0[c], bb = r1[c], cc = r2[c];
    float4 o;
    o.x = f2tf32f(fmaf(a.x, w0, fmaf(bb.x, w1, cc.x * w2)));
    o.y = f2tf32f(fmaf(a.y, w0, fmaf(bb.y, w1, cc.y * w2)));
    o.z = f2tf32f(fmaf(a.z, w0, fmaf(bb.z, w1, cc.z * w2)));
    o.w = f2tf32f(fmaf(a.w, w0, fmaf(bb.w, w1, cc.w * w2)));
    h[64 + c] = o;
}

// ---------------------------------------------------------------------------
// GEMM0: C[M, NT] = A[M, KT] @ B[NT, KT]^T + bias  (A, B pre-rounded tf32 bits)
// Block tile 128x128, BK=32, double-buffered cp.async, ONE sync per chunk:
//   CP_WAIT(0); sync; issue load(kt+1); compute(kt)
// All writes to buffer (kt+1)&1 happen AFTER the sync that proves compute(kt-1)
// (its last reader) finished in every warp.
// ---------------------------------------------------------------------------
template<int NT, int KT>
__global__ __launch_bounds__(256)
void mma_gemm_kernel(const float* __restrict__ A, const float* __restrict__ Bw,
                     const float* __restrict__ bias, float* __restrict__ C) {
    constexpr int NC    = KT / 32;
    constexpr int LDT   = 36;             // padded row stride (floats)
    constexpr int STAGE = 2 * 128 * LDT;  // floats per stage (A then B)

    extern __shared__ float sm[];
    const uint32_t smb = smem_u32(sm);

    const int tid    = threadIdx.x;
    const int wid    = tid >> 5;
    const int lane   = tid & 31;
    const int g      = lane >> 2;
    const int tg     = lane & 3;
    const int warp_m = wid >> 1;
    const int warp_n = wid & 1;
    const size_t bm  = (size_t)blockIdx.y * 128;
    const size_t bn  = (size_t)blockIdx.x * 128;

    float acc[2][8][4];
    #pragma unroll
    for (int mt = 0; mt < 2; mt++)
        #pragma unroll
        for (int nt = 0; nt < 8; nt++)
            #pragma unroll
            for (int i = 0; i < 4; i++) acc[mt][nt][i] = 0.0f;

    auto load_stage = [&](int kt, int s) {
        const float* Ag = A + bm * KT + kt * 32;
        const float* Bg = Bw + bn * KT + kt * 32;
        const uint32_t base = smb + (uint32_t)(s * STAGE) * 4u;
        #pragma unroll
        for (int i = 0; i < 4; i++) {
            int id = i * 256 + tid;
            int r = id >> 3, kk = (id & 7) * 4;
            CP_ASYNC16(base + (r * LDT + kk) * 4, Ag + (size_t)r * KT + kk);
        }
        #pragma unroll
        for (int i = 0; i < 4; i++) {
            int id = i * 256 + tid;
            int r = id >> 3, kk = (id & 7) * 4;
            CP_ASYNC16(base + (128 * LDT + r * LDT + kk) * 4, Bg + (size_t)r * KT + kk);
        }
        CP_COMMIT();
    };

    load_stage(0, 0);

    for (int kt = 0; kt < NC; kt++) {
        CP_WAIT(0);          // stage kt landed (only pending group)
        __syncthreads();     // publish stage kt; all warps done with buf (kt+1)&1
        if (kt + 1 < NC) load_stage(kt + 1, (kt + 1) & 1);  // overlaps compute

        const uint32_t* as = (const uint32_t*)sm + (kt & 1) * STAGE + (warp_m * 32) * LDT;
        const uint32_t* bs = (const uint32_t*)sm + (kt & 1) * STAGE + 128 * LDT
                           + (warp_n * 64) * LDT;

        #pragma unroll
        for (int kc = 0; kc < 4; kc++) {
            uint32_t a[2][4];
            #pragma unroll
            for (int mt = 0; mt < 2; mt++) {
                int base = (mt * 16 + g) * LDT + kc * 8 + tg;
                a[mt][0] = as[base];
                a[mt][1] = as[base + 8 * LDT];
                a[mt][2] = as[base + 4];
                a[mt][3] = as[base + 8 * LDT + 4];
            }
            #pragma unroll
            for (int nt = 0; nt < 8; nt++) {
                uint32_t b[2];
                int bb = (nt * 8 + g) * LDT + kc * 8 + tg;
                b[0] = bs[bb];
                b[1] = bs[bb + 4];
                mma_tf32_16x8x8(acc[0][nt], a[0], b);
                mma_tf32_16x8x8(acc[1][nt], a[1], b);
            }
        }
    }

    #pragma unroll
    for (int mt = 0; mt < 2; mt++) {
        #pragma unroll
        for (int nt = 0; nt < 8; nt++) {
            size_t col = bn + warp_n * 64 + nt * 8 + 2 * tg;
            float bi0 = __ldg(&bias[col]), bi1 = __ldg(&bias[col + 1]);
            size_t r0 = bm + warp_m * 32 + mt * 16 + g;
            float2 v0 = make_float2(acc[mt][nt][0] + bi0, acc[mt][nt][1] + bi1);
            float2 v1 = make_float2(acc[mt][nt][2] + bi0, acc[mt][nt][3] + bi1);
            *(float2*)(C + r0 * NT + col)       = v0;
            *(float2*)(C + (r0 + 8) * NT + col) = v1;
        }
    }
}

// ---------------------------------------------------------------------------
// GEMM1 with fused BN0+ReLU+tf32 on the A operand:
//   C[M,128] = relu(s0*Y0 + t0) @ W1^T + b1
// RACE-FIX vs R5: ALL writes into buffer (kt+1)&1 (A LDG->STS staging and
// B cp.async) are issued AFTER the iteration's __syncthreads(), which proves
// every warp finished compute(kt-1), the last reader of that buffer.
// ---------------------------------------------------------------------------
template<int NT, int KT>
__global__ __launch_bounds__(256, 2)
void mma_gemm_act_kernel(const float* __restrict__ A, const float* __restrict__ Bw,
                         const float* __restrict__ bias,
                         const float* __restrict__ sc, const float* __restrict__ shf,
                         float* __restrict__ C) {
    constexpr int NC    = KT / 32;
    constexpr int LDT   = 36;
    constexpr int STAGE = 2 * 128 * LDT;

    extern __shared__ float sm[];
    const uint32_t smb = smem_u32(sm);

    const int tid    = threadIdx.x;
    const int wid    = tid >> 5;
    const int lane   = tid & 31;
    const int g      = lane >> 2;
    const int tg     = lane & 3;
    const int warp_m = wid >> 1;
    const int warp_n = wid & 1;
    const size_t bm  = (size_t)blockIdx.y * 128;
    const size_t bn  = (size_t)blockIdx.x * 128;

    const int lr = tid >> 1;              // A-load row 0..127
    const int lk = (tid & 1) * 16;        // A-load k-offset 0 or 16

    float acc[2][8][4];
    #pragma unroll
    for (int mt = 0; mt < 2; mt++)
        #pragma unroll
        for (int nt = 0; nt < 8; nt++)
            #pragma unroll
            for (int i = 0; i < 4; i++) acc[mt][nt][i] = 0.0f;

    auto load_a_regs = [&](int kt, float4* av) {
        const float* Ag = A + (size_t)(bm + lr) * KT + kt * 32 + lk;
        #pragma unroll
        for (int i = 0; i < 4; i++) av[i] = *(const float4*)(Ag + 4 * i);
    };
    auto store_a = [&](int kt, int s, const float4* av) {
        const int c0 = kt * 32 + lk;
        float* dst = sm + s * STAGE + lr * LDT + lk;
        #pragma unroll
        for (int i = 0; i < 4; i++) {
            float4 s4 = *(const float4*)(sc  + c0 + 4 * i);
            float4 t4 = *(const float4*)(shf + c0 + 4 * i);
            float4 v;
            v.x = f2tf32f(fmaxf(0.0f, fmaf(av[i].x, s4.x, t4.x)));
            v.y = f2tf32f(fmaxf(0.0f, fmaf(av[i].y, s4.y, t4.y)));
            v.z = f2tf32f(fmaxf(0.0f, fmaf(av[i].z, s4.z, t4.z)));
            v.w = f2tf32f(fmaxf(0.0f, fmaf(av[i].w, s4.w, t4.w)));
            *(float4*)(dst + 4 * i) = v;
        }
    };
    auto load_b_stage = [&](int kt, int s) {
        const float* Bg = Bw + bn * KT + kt * 32;
        const uint32_t base = smb + (uint32_t)(s * STAGE + 128 * LDT) * 4u;
        #pragma unroll
        for (int i = 0; i < 4; i++) {
            int id = i * 256 + tid;
            int r = id >> 3, kk = (id & 7) * 4;
            CP_ASYNC16(base + (r * LDT + kk) * 4, Bg + (size_t)r * KT + kk);
        }
        CP_COMMIT();
    };

    // prologue: stage 0 (A staged via regs+STS, B via cp.async)
    {
        float4 av[4];
        load_a_regs(0, av);
        load_b_stage(0, 0);
        store_a(0, 0, av);
    }

    for (int kt = 0; kt < NC; kt++) {
        CP_WAIT(0);          // B(kt) landed (only pending group)
        __syncthreads();     // publish stage kt; all warps done with buf (kt+1)&1

        float4 av[4];
        if (kt + 1 < NC) {
            load_a_regs(kt + 1, av);              // LDG overlaps compute(kt)
            load_b_stage(kt + 1, (kt + 1) & 1);   // safe: past the sync
        }

        const uint32_t* as = (const uint32_t*)sm + (kt & 1) * STAGE + (warp_m * 32) * LDT;
        const uint32_t* bs = (const uint32_t*)sm + (kt & 1) * STAGE + 128 * LDT
                           + (warp_n * 64) * LDT;

        #pragma unroll
        for (int kc = 0; kc < 4; kc++) {
            uint32_t a[2][4];
            #pragma unroll
            for (int mt = 0; mt < 2; mt++) {
                int base = (mt * 16 + g) * LDT + kc * 8 + tg;
                a[mt][0] = as[base];
                a[mt][1] = as[base + 8 * LDT];
                a[mt][2] = as[base + 4];
                a[mt][3] = as[base + 8 * LDT + 4];
            }
            #pragma unroll
            for (int nt = 0; nt < 8; nt++) {
                uint32_t b[2];
                int bb = (nt * 8 + g) * LDT + kc * 8 + tg;
                b[0] = bs[bb];
                b[1] = bs[bb + 4];
                mma_tf32_16x8x8(acc[0][nt], a[0], b);
                mma_tf32_16x8x8(acc[1][nt], a[1], b);
            }
        }

        if (kt + 1 < NC) store_a(kt + 1, (kt + 1) & 1, av);  // published by next sync
    }

    #pragma unroll
    for (int mt = 0; mt < 2; mt++) {
        #pragma unroll
        for (int nt = 0; nt < 8; nt++) {
            size_t col = bn + warp_n * 64 + nt * 8 + 2 * tg;
            float bi0 = __ldg(&bias[col]), bi1 = __ldg(&bias[col + 1]);
            size_t r0 = bm + warp_m * 32 + mt * 16 + g;
            float2 v0 = make_float2(acc[mt][nt][0] + bi0, acc[mt][nt][1] + bi1);
            float2 v1 = make_float2(acc[mt][nt][2] + bi0, acc[mt][nt][3] + bi1);
            *(float2*)(C + r0 * NT + col)       = v0;
            *(float2*)(C + (r0 + 8) * NT + col) = v1;
        }
    }
}

// ---------------------------------------------------------------------------
// Stats / BN kernels
// ---------------------------------------------------------------------------
template<int C, int R>
__global__ void stats_kernel(const float* __restrict__ Y,
                             double* __restrict__ Sum, double* __restrict__ Ss) {
    const int c = threadIdx.x;
    const float* p = Y + (size_t)blockIdx.x * R * C + c;
    double s = 0.0, ss = 0.0;
    #pragma unroll 4
    for (int r = 0; r < R; r++) {
        float v = p[(size_t)r * C];
        s  += (double)v;
        ss += (double)v * (double)v;
    }
    atomicAdd(&Sum[c], s);
    atomicAdd(&Ss[c],  ss);
}

__global__ void finalize_kernel(const double* __restrict__ Sum,
                                const double* __restrict__ Ss,
                                const float* __restrict__ gamma,
                                const float* __restrict__ beta,
                                float* __restrict__ sc, float* __restrict__ shf,
                                int C) {
    int c = threadIdx.x;
    if (c < C) {
        double mean = Sum[c] * (1.0 / (double)MM);
        double var  = Ss[c]  * (1.0 / (double)MM) - mean * mean;
        float s = gamma[c] * rsqrtf((float)var + BNEPS);
        sc[c]  = s;
        shf[c] = beta[c] - (float)mean * s;
    }
}

// final BN+ReLU in place on d_out (layer 1)
__global__ void act_kernel(float* __restrict__ Y,
                           const float* __restrict__ sc,
                           const float* __restrict__ shf) {
    int i = blockIdx.x * blockDim.x + threadIdx.x;
    float4 v = ((float4*)Y)[i];
    const float4 s4 = ((const float4*)sc)[i & 31];   // H1/4 = 32
    const float4 t4 = ((const float4*)shf)[i & 31];
    v.x = fmaxf(0.0f, fmaf(v.x, s4.x, t4.x));
    v.y = fmaxf(0.0f, fmaf(v.y, s4.y, t4.y));
    v.z = fmaxf(0.0f, fmaf(v.z, s4.z, t4.z));
    v.w = fmaxf(0.0f, fmaf(v.w, s4.w, t4.w));
    ((float4*)Y)[i] = v;
}

// ---------------------------------------------------------------------------
// Launch sequence
// ---------------------------------------------------------------------------
extern "C" void kernel_launch(void* const* d_in, const int* in_sizes, int n_in,
                              void* d_out, int out_size) {
    const float* xyz1    = (const float*)d_in[0];
    const float* xyz2    = (const float*)d_in[1];
    const float* points1 = (const float*)d_in[2];
    const float* points2 = (const float*)d_in[3];
    const float* rel_w   = (const float*)d_in[4];
    const float* rel_b   = (const float*)d_in[5];
    const float* W0      = (const float*)d_in[6];
    const float* b0      = (const float*)d_in[7];
    const float* g0      = (const float*)d_in[8];
    const float* be0     = (const float*)d_in[9];
    const float* W1      = (const float*)d_in[10];
    const float* b1      = (const float*)d_in[11];
    const float* g1      = (const float*)d_in[12];
    const float* be1     = (const float*)d_in[13];
    float* out = (float*)d_out;

    float *p_h, *p_y0, *p_w0t, *p_w1t, *p_s0, *p_t0, *p_s1, *p_t1;
    double *p_sum0, *p_ss0, *p_sum1, *p_ss1;
    cudaGetSymbolAddress((void**)&p_h,    g_h);
    cudaGetSymbolAddress((void**)&p_y0,   g_y0);
    cudaGetSymbolAddress((void**)&p_w0t,  g_w0t);
    cudaGetSymbolAddress((void**)&p_w1t,  g_w1t);
    cudaGetSymbolAddress((void**)&p_s0,   g_s0);
    cudaGetSymbolAddress((void**)&p_t0,   g_t0);
    cudaGetSymbolAddress((void**)&p_s1,   g_s1);
    cudaGetSymbolAddress((void**)&p_t1,   g_t1);
    cudaGetSymbolAddress((void**)&p_sum0, g_sum0);
    cudaGetSymbolAddress((void**)&p_ss0,  g_ss0);
    cudaGetSymbolAddress((void**)&p_sum1, g_sum1);
    cudaGetSymbolAddress((void**)&p_ss1,  g_ss1);

    const int smem = 2 * 2 * 128 * 36 * 4;   // 73728 B
    cudaFuncSetAttribute(mma_gemm_kernel<H0, K0>,
                         cudaFuncAttributeMaxDynamicSharedMemorySize, smem);
    cudaFuncSetAttribute(mma_gemm_act_kernel<H1, H0>,
                         cudaFuncAttributeMaxDynamicSharedMemorySize, smem);

    zero_stats_kernel<<<1, 256>>>();
    convert_w_kernel<<<(H0 * K0 + 255) / 256, 256>>>(W0, W1);
    knn_kernel<<<dim3(NN / 256, BB), 256>>>(xyz1, xyz2, rel_w, rel_b);
    interp_kernel<<<MM / 4, 256>>>(points1, points2);

    // layer 0: h[M,512] @ W0[256,512]^T + b0 -> y0
    mma_gemm_kernel<H0, K0><<<dim3(H0 / 128, MM / 128), 256, smem>>>(p_h, p_w0t, b0, p_y0);
    stats_kernel<H0, 256><<<MM / 256, H0>>>(p_y0, p_sum0, p_ss0);
    finalize_kernel<<<1, H0>>>(p_sum0, p_ss0, g0, be0, p_s0, p_t0, H0);

    // layer 1 (fused BN0+ReLU on A): relu(s0*y0+t0)[M,256] @ W1^T + b1 -> out
    mma_gemm_act_kernel<H1, H0><<<dim3(H1 / 128, MM / 128), 256, smem>>>(
        p_y0, p_w1t, b1, p_s0, p_t0, out);
    stats_kernel<H1, 512><<<MM / 512, H1>>>(out, p_sum1, p_ss1);
    finalize_kernel<<<1, H1>>>(p_sum1, p_ss1, g1, be1, p_s1, p_t1, H1);

    act_kernel<<<(MM * H1 / 4) / 256, 256>>>(out, p_s1, p_t1);
}

// round 7
// speedup vs baseline: 2.2643x; 1.2891x over previous
#include <cuda_runtime.h>
#include <math.h>
#include <stdint.h>

// Problem constants
#define BB   8
#define NN   8192
#define SS   2048
#define DD   256
#define MM   65536      // BB*NN
#define H0   256
#define H1   128
#define K0   512        // 2*DD
#define BNEPS 1e-5f

// ---------------------------------------------------------------------------
// Scratch
// ---------------------------------------------------------------------------
__device__ float  g_h  [(size_t)MM * K0];   // concat(points1, interp), tf32 bits
__device__ float  g_y0 [(size_t)MM * H0];   // layer0 pre-BN output (fp32)
__device__ float  g_w0t[H0 * K0];           // W0 as tf32 bits
__device__ float  g_w1t[H1 * H0];           // W1 as tf32 bits
__device__ int    g_idx[MM * 3];
__device__ float  g_w  [MM * 3];
__device__ double g_sum0[H0], g_ss0[H0], g_sum1[H1], g_ss1[H1];
__device__ float  g_s0[H0], g_t0[H0], g_s1[H1], g_t1[H1];

// ---------------------------------------------------------------------------
// Portable PTX helpers (toolchain targets sm_103 — no arch-accelerated instrs)
// ---------------------------------------------------------------------------
__device__ __forceinline__ uint32_t smem_u32(const void* p) {
    uint32_t a;
    asm("{ .reg .u64 t; cvta.to.shared.u64 t, %1; cvt.u32.u64 %0, t; }" : "=r"(a) : "l"(p));
    return a;
}

#define CP_ASYNC16(dst, src) \
    asm volatile("cp.async.cg.shared.global [%0], [%1], 16;" :: "r"(dst), "l"(src) : "memory")
#define CP_COMMIT() asm volatile("cp.async.commit_group;" ::: "memory")
#define CP_WAIT(n)  asm volatile("cp.async.wait_group %0;" :: "n"(n) : "memory")

__device__ __forceinline__ float f2tf32f(float x) {
    uint32_t r;
    asm("cvt.rna.tf32.f32 %0, %1;" : "=r"(r) : "f"(x));
    return __uint_as_float(r);
}

__device__ __forceinline__ void mma_tf32_16x8x8(float* c, const uint32_t* a,
                                                const uint32_t* b) {
    asm volatile(
        "mma.sync.aligned.m16n8k8.row.col.f32.tf32.tf32.f32 "
        "{%0,%1,%2,%3}, {%4,%5,%6,%7}, {%8,%9}, {%0,%1,%2,%3};"
        : "+f"(c[0]), "+f"(c[1]), "+f"(c[2]), "+f"(c[3])
        : "r"(a[0]), "r"(a[1]), "r"(a[2]), "r"(a[3]), "r"(b[0]), "r"(b[1]));
}

// ---------------------------------------------------------------------------
// Misc small kernels
// ---------------------------------------------------------------------------
__global__ void zero_stats_kernel() {
    int t = threadIdx.x;
    if (t < H0) { g_sum0[t] = 0.0; g_ss0[t] = 0.0; }
    if (t < H1) { g_sum1[t] = 0.0; g_ss1[t] = 0.0; }
}

__global__ void convert_w_kernel(const float* __restrict__ W0,
                                 const float* __restrict__ W1) {
    int i = blockIdx.x * blockDim.x + threadIdx.x;
    if (i < H0 * K0) g_w0t[i] = f2tf32f(W0[i]);
    if (i < H1 * H0) g_w1t[i] = f2tf32f(W1[i]);
}

// KNN: 128 threads/block, each thread handles 2 query points (tid, tid+128).
// Per-point arithmetic identical to the 1-pt version (same idx/weights).
__global__ void knn_kernel(const float* __restrict__ xyz1,
                           const float* __restrict__ xyz2,
                           const float* __restrict__ rel_w,
                           const float* __restrict__ rel_b) {
    __shared__ float4 sh[SS];
    const int b = blockIdx.y;
    const float* x2 = xyz2 + (size_t)b * SS * 3;
    for (int s = threadIdx.x; s < SS; s += 128) {
        float x = x2[s * 3 + 0], y = x2[s * 3 + 1], z = x2[s * 3 + 2];
        sh[s] = make_float4(x, y, z, x * x + y * y + z * z);
    }
    __syncthreads();

    const int nA = blockIdx.x * 256 + threadIdx.x;
    const int gA = b * NN + nA;
    const int gB = gA + 128;

    const float ax = xyz1[(size_t)gA * 3 + 0];
    const float ay = xyz1[(size_t)gA * 3 + 1];
    const float az = xyz1[(size_t)gA * 3 + 2];
    const float an = ax * ax + ay * ay + az * az;
    const float bx = xyz1[(size_t)gB * 3 + 0];
    const float by = xyz1[(size_t)gB * 3 + 1];
    const float bz = xyz1[(size_t)gB * 3 + 2];
    const float bn = bx * bx + by * by + bz * bz;

    float ad0 = 3.4e38f, ad1 = 3.4e38f, ad2 = 3.4e38f;
    int   ai0 = 0, ai1 = 0, ai2 = 0;
    float bd0 = 3.4e38f, bd1 = 3.4e38f, bd2 = 3.4e38f;
    int   bi0 = 0, bi1 = 0, bi2 = 0;

    #pragma unroll 4
    for (int s = 0; s < SS; s++) {
        float4 p = sh[s];
        float da = (an + p.w) - 2.0f * (ax * p.x + ay * p.y + az * p.z);
        float db = (bn + p.w) - 2.0f * (bx * p.x + by * p.y + bz * p.z);
        if (da < ad2) {
            if (da < ad1) {
                ad2 = ad1; ai2 = ai1;
                if (da < ad0) { ad1 = ad0; ai1 = ai0; ad0 = da; ai0 = s; }
                else          { ad1 = da;  ai1 = s; }
            } else { ad2 = da; ai2 = s; }
        }
        if (db < bd2) {
            if (db < bd1) {
                bd2 = bd1; bi2 = bi1;
                if (db < bd0) { bd1 = bd0; bi1 = bi0; bd0 = db; bi0 = s; }
                else          { bd1 = db;  bi1 = s; }
            } else { bd2 = db; bi2 = s; }
        }
    }

    const float rw0 = rel_w[0], rw1 = rel_w[1], rw2 = rel_w[2], rw3 = rel_w[3];
    const float rb  = rel_b[0];
    {
        int   is[3] = { ai0, ai1, ai2 };
        float ds[3] = { ad0, ad1, ad2 };
        #pragma unroll
        for (int k = 0; k < 3; k++) {
            float4 p = sh[is[k]];
            float ox = ax - p.x, oy = ay - p.y, oz = az - p.z;
            float zl = ds[k] * rw0 + ox * rw1 + oy * rw2 + oz * rw3 + rb;
            float w = 1.0f / (1.0f + expf(-zl));
            g_idx[gA * 3 + k] = is[k];
            g_w[gA * 3 + k]   = w * (1.0f / 3.0f);
        }
    }
    {
        int   is[3] = { bi0, bi1, bi2 };
        float ds[3] = { bd0, bd1, bd2 };
        #pragma unroll
        for (int k = 0; k < 3; k++) {
            float4 p = sh[is[k]];
            float ox = bx - p.x, oy = by - p.y, oz = bz - p.z;
            float zl = ds[k] * rw0 + ox * rw1 + oy * rw2 + oz * rw3 + rb;
            float w = 1.0f / (1.0f + expf(-zl));
            g_idx[gB * 3 + k] = is[k];
            g_w[gB * 3 + k]   = w * (1.0f / 3.0f);
        }
    }
}

// interp + concat; writes tf32-rounded bit patterns (GEMM0 consumes directly)
__global__ void interp_kernel(const float* __restrict__ points1,
                              const float* __restrict__ points2) {
    const int gn = blockIdx.x * 4 + (threadIdx.x >> 6);
    const int c  = threadIdx.x & 63;      // float4 index within row
    const int b  = gn >> 13;
    const float* p2b = points2 + (size_t)b * SS * DD;

    const int   j0 = g_idx[gn * 3 + 0], j1 = g_idx[gn * 3 + 1], j2 = g_idx[gn * 3 + 2];
    const float w0 = g_w[gn * 3 + 0],  w1 = g_w[gn * 3 + 1],  w2 = g_w[gn * 3 + 2];

    const float4* r0 = (const float4*)(p2b + (size_t)j0 * DD);
    const float4* r1 = (const float4*)(p2b + (size_t)j1 * DD);
    const float4* r2 = (const float4*)(p2b + (size_t)j2 * DD);
    const float4* q  = (const float4*)(points1 + (size_t)gn * DD);
    float4* h = (float4*)(g_h + (size_t)gn * K0);

    float4 p1 = q[c];
    p1.x = f2tf32f(p1.x); p1.y = f2tf32f(p1.y);
    p1.z = f2tf32f(p1.z); p1.w = f2tf32f(p1.w);
    h[c] = p1;

    float4 a = r0[c], bb = r1[c], cc = r2[c];
    float4 o;
    o.x = f2tf32f(fmaf(a.x, w0, fmaf(bb.x, w1, cc.x * w2)));
    o.y = f2tf32f(fmaf(a.y, w0, fmaf(bb.y, w1, cc.y * w2)));
    o.z = f2tf32f(fmaf(a.z, w0, fmaf(bb.z, w1, cc.z * w2)));
    o.w = f2tf32f(fmaf(a.w, w0, fmaf(bb.w, w1, cc.w * w2)));
    h[64 + c] = o;
}

// ---------------------------------------------------------------------------
// GEMM0: y0[M,256] = h[M,512] @ W0^T + b0, fused per-channel stats.
// Block tile 128x256 (FULL N -> A read once from DRAM), 512 threads,
// 16 warps as 4Mx4N, warp tile 32x64. BK=32, double-buffered cp.async,
// one sync per chunk.
// ---------------------------------------------------------------------------
__global__ __launch_bounds__(512)
void gemm0_kernel(const float* __restrict__ A, const float* __restrict__ Bw,
                  const float* __restrict__ bias, float* __restrict__ C,
                  double* __restrict__ Sum, double* __restrict__ Ss) {
    constexpr int KT    = K0;             // 512
    constexpr int NT    = H0;             // 256
    constexpr int NC    = KT / 32;        // 16
    constexpr int LDT   = 36;
    constexpr int STAGE = (128 + NT) * LDT;   // A rows then B rows

    extern __shared__ float sm[];
    const uint32_t smb = smem_u32(sm);

    const int tid    = threadIdx.x;
    const int wid    = tid >> 5;
    const int lane   = tid & 31;
    const int g      = lane >> 2;
    const int tg     = lane & 3;
    const int warp_m = wid >> 2;          // 0..3
    const int warp_n = wid & 3;           // 0..3
    const size_t bm  = (size_t)blockIdx.x * 128;

    float acc[2][8][4];
    #pragma unroll
    for (int mt = 0; mt < 2; mt++)
        #pragma unroll
        for (int nt = 0; nt < 8; nt++)
            #pragma unroll
            for (int i = 0; i < 4; i++) acc[mt][nt][i] = 0.0f;

    auto load_stage = [&](int kt, int s) {
        const float* Ag = A + bm * KT + kt * 32;
        const float* Bg = Bw + kt * 32;
        const uint32_t base = smb + (uint32_t)(s * STAGE) * 4u;
        #pragma unroll
        for (int i = 0; i < 2; i++) {                     // A: 1024 float4
            int id = i * 512 + tid;
            int r = id >> 3, kk = (id & 7) * 4;
            CP_ASYNC16(base + (r * LDT + kk) * 4, Ag + (size_t)r * KT + kk);
        }
        #pragma unroll
        for (int i = 0; i < 4; i++) {                     // B: 2048 float4
            int id = i * 512 + tid;
            int r = id >> 3, kk = (id & 7) * 4;
            CP_ASYNC16(base + (128 * LDT + r * LDT + kk) * 4, Bg + (size_t)r * KT + kk);
        }
        CP_COMMIT();
    };

    load_stage(0, 0);

    for (int kt = 0; kt < NC; kt++) {
        CP_WAIT(0);
        __syncthreads();
        if (kt + 1 < NC) load_stage(kt + 1, (kt + 1) & 1);

        const uint32_t* as = (const uint32_t*)sm + (kt & 1) * STAGE + (warp_m * 32) * LDT;
        const uint32_t* bs = (const uint32_t*)sm + (kt & 1) * STAGE + 128 * LDT
                           + (warp_n * 64) * LDT;

        #pragma unroll
        for (int kc = 0; kc < 4; kc++) {
            uint32_t a[2][4];
            #pragma unroll
            for (int mt = 0; mt < 2; mt++) {
                int base = (mt * 16 + g) * LDT + kc * 8 + tg;
                a[mt][0] = as[base];
                a[mt][1] = as[base + 8 * LDT];
                a[mt][2] = as[base + 4];
                a[mt][3] = as[base + 8 * LDT + 4];
            }
            #pragma unroll
            for (int nt = 0; nt < 8; nt++) {
                uint32_t b[2];
                int bb = (nt * 8 + g) * LDT + kc * 8 + tg;
                b[0] = bs[bb];
                b[1] = bs[bb + 4];
                mma_tf32_16x8x8(acc[0][nt], a[0], b);
                mma_tf32_16x8x8(acc[1][nt], a[1], b);
            }
        }
    }

    // smem reuse for per-channel stats partials
    __syncthreads();
    if (tid < NT) { sm[tid] = 0.0f; sm[NT + tid] = 0.0f; }
    __syncthreads();

    #pragma unroll
    for (int nt = 0; nt < 8; nt++) {
        int col = warp_n * 64 + nt * 8 + 2 * tg;
        float bi0 = __ldg(&bias[col]), bi1 = __ldg(&bias[col + 1]);
        float s0 = 0.f, s1 = 0.f, q0 = 0.f, q1 = 0.f;
        #pragma unroll
        for (int mt = 0; mt < 2; mt++) {
            size_t r0 = bm + warp_m * 32 + mt * 16 + g;
            float v0x = acc[mt][nt][0] + bi0, v0y = acc[mt][nt][1] + bi1;
            float v1x = acc[mt][nt][2] + bi0, v1y = acc[mt][nt][3] + bi1;
            *(float2*)(C + r0 * NT + col)       = make_float2(v0x, v0y);
            *(float2*)(C + (r0 + 8) * NT + col) = make_float2(v1x, v1y);
            s0 += v0x + v1x;  s1 += v0y + v1y;
            q0 += v0x * v0x + v1x * v1x;
            q1 += v0y * v0y + v1y * v1y;
        }
        #pragma unroll
        for (int d = 4; d < 32; d <<= 1) {     // reduce over g lanes
            s0 += __shfl_xor_sync(0xffffffffu, s0, d);
            s1 += __shfl_xor_sync(0xffffffffu, s1, d);
            q0 += __shfl_xor_sync(0xffffffffu, q0, d);
            q1 += __shfl_xor_sync(0xffffffffu, q1, d);
        }
        if (lane < 4) {
            int c = warp_n * 64 + nt * 8 + 2 * lane;
            atomicAdd(&sm[c],          s0);
            atomicAdd(&sm[c + 1],      s1);
            atomicAdd(&sm[NT + c],     q0);
            atomicAdd(&sm[NT + c + 1], q1);
        }
    }
    __syncthreads();
    if (tid < NT) {
        atomicAdd(&Sum[tid], (double)sm[tid]);
        atomicAdd(&Ss[tid],  (double)sm[NT + tid]);
    }
}

// ---------------------------------------------------------------------------
// GEMM1 with fused BN0+ReLU+tf32 on A and fused stats on the output:
//   out[M,128] = relu(s0*Y0 + t0) @ W1^T + b1
// 256 threads, block tile 128x128 (full N), 8 warps 4Mx2N.
// ---------------------------------------------------------------------------
__global__ __launch_bounds__(256, 2)
void gemm1_kernel(const float* __restrict__ A, const float* __restrict__ Bw,
                  const float* __restrict__ bias,
                  const float* __restrict__ sc, const float* __restrict__ shf,
                  float* __restrict__ C,
                  double* __restrict__ Sum, double* __restrict__ Ss) {
    constexpr int KT    = H0;             // 256
    constexpr int NT    = H1;             // 128
    constexpr int NC    = KT / 32;        // 8
    constexpr int LDT   = 36;
    constexpr int STAGE = 2 * 128 * LDT;

    extern __shared__ float sm[];
    const uint32_t smb = smem_u32(sm);

    const int tid    = threadIdx.x;
    const int wid    = tid >> 5;
    const int lane   = tid & 31;
    const int g      = lane >> 2;
    const int tg     = lane & 3;
    const int warp_m = wid >> 1;
    const int warp_n = wid & 1;
    const size_t bm  = (size_t)blockIdx.x * 128;

    const int lr = tid >> 1;
    const int lk = (tid & 1) * 16;

    float acc[2][8][4];
    #pragma unroll
    for (int mt = 0; mt < 2; mt++)
        #pragma unroll
        for (int nt = 0; nt < 8; nt++)
            #pragma unroll
            for (int i = 0; i < 4; i++) acc[mt][nt][i] = 0.0f;

    auto load_a_regs = [&](int kt, float4* av) {
        const float* Ag = A + (size_t)(bm + lr) * KT + kt * 32 + lk;
        #pragma unroll
        for (int i = 0; i < 4; i++) av[i] = *(const float4*)(Ag + 4 * i);
    };
    auto store_a = [&](int kt, int s, const float4* av) {
        const int c0 = kt * 32 + lk;
        float* dst = sm + s * STAGE + lr * LDT + lk;
        #pragma unroll
        for (int i = 0; i < 4; i++) {
            float4 s4 = *(const float4*)(sc  + c0 + 4 * i);
            float4 t4 = *(const float4*)(shf + c0 + 4 * i);
            float4 v;
            v.x = f2tf32f(fmaxf(0.0f, fmaf(av[i].x, s4.x, t4.x)));
            v.y = f2tf32f(fmaxf(0.0f, fmaf(av[i].y, s4.y, t4.y)));
            v.z = f2tf32f(fmaxf(0.0f, fmaf(av[i].z, s4.z, t4.z)));
            v.w = f2tf32f(fmaxf(0.0f, fmaf(av[i].w, s4.w, t4.w)));
            *(float4*)(dst + 4 * i) = v;
        }
    };
    auto load_b_stage = [&](int kt, int s) {
        const float* Bg = Bw + kt * 32;
        const uint32_t base = smb + (uint32_t)(s * STAGE + 128 * LDT) * 4u;
        #pragma unroll
        for (int i = 0; i < 4; i++) {
            int id = i * 256 + tid;
            int r = id >> 3, kk = (id & 7) * 4;
            CP_ASYNC16(base + (r * LDT + kk) * 4, Bg + (size_t)r * KT + kk);
        }
        CP_COMMIT();
    };

    {
        float4 av[4];
        load_a_regs(0, av);
        load_b_stage(0, 0);
        store_a(0, 0, av);
    }

    for (int kt = 0; kt < NC; kt++) {
        CP_WAIT(0);
        __syncthreads();

        float4 av[4];
        if (kt + 1 < NC) {
            load_a_regs(kt + 1, av);
            load_b_stage(kt + 1, (kt + 1) & 1);
        }

        const uint32_t* as = (const uint32_t*)sm + (kt & 1) * STAGE + (warp_m * 32) * LDT;
        const uint32_t* bs = (const uint32_t*)sm + (kt & 1) * STAGE + 128 * LDT
                           + (warp_n * 64) * LDT;

        #pragma unroll
        for (int kc = 0; kc < 4; kc++) {
            uint32_t a[2][4];
            #pragma unroll
            for (int mt = 0; mt < 2; mt++) {
                int base = (mt * 16 + g) * LDT + kc * 8 + tg;
                a[mt][0] = as[base];
                a[mt][1] = as[base + 8 * LDT];
                a[mt][2] = as[base + 4];
                a[mt][3] = as[base + 8 * LDT + 4];
            }
            #pragma unroll
            for (int nt = 0; nt < 8; nt++) {
                uint32_t b[2];
                int bb = (nt * 8 + g) * LDT + kc * 8 + tg;
                b[0] = bs[bb];
                b[1] = bs[bb + 4];
                mma_tf32_16x8x8(acc[0][nt], a[0], b);
                mma_tf32_16x8x8(acc[1][nt], a[1], b);
            }
        }

        if (kt + 1 < NC) store_a(kt + 1, (kt + 1) & 1, av);
    }

    // smem reuse for stats partials
    __syncthreads();
    if (tid < NT) { sm[tid] = 0.0f; sm[NT + tid] = 0.0f; }
    __syncthreads();

    #pragma unroll
    for (int nt = 0; nt < 8; nt++) {
        int col = warp_n * 64 + nt * 8 + 2 * tg;
        float bi0 = __ldg(&bias[col]), bi1 = __ldg(&bias[col + 1]);
        float s0 = 0.f, s1 = 0.f, q0 = 0.f, q1 = 0.f;
        #pragma unroll
        for (int mt = 0; mt < 2; mt++) {
            size_t r0 = bm + warp_m * 32 + mt * 16 + g;
            float v0x = acc[mt][nt][0] + bi0, v0y = acc[mt][nt][1] + bi1;
            float v1x = acc[mt][nt][2] + bi0, v1y = acc[mt][nt][3] + bi1;
            *(float2*)(C + r0 * NT + col)       = make_float2(v0x, v0y);
            *(float2*)(C + (r0 + 8) * NT + col) = make_float2(v1x, v1y);
            s0 += v0x + v1x;  s1 += v0y + v1y;
            q0 += v0x * v0x + v1x * v1x;
            q1 += v0y * v0y + v1y * v1y;
        }
        #pragma unroll
        for (int d = 4; d < 32; d <<= 1) {
            s0 += __shfl_xor_sync(0xffffffffu, s0, d);
            s1 += __shfl_xor_sync(0xffffffffu, s1, d);
            q0 += __shfl_xor_sync(0xffffffffu, q0, d);
            q1 += __shfl_xor_sync(0xffffffffu, q1, d);
        }
        if (lane < 4) {
            int c = warp_n * 64 + nt * 8 + 2 * lane;
            atomicAdd(&sm[c],          s0);
            atomicAdd(&sm[c + 1],      s1);
            atomicAdd(&sm[NT + c],     q0);
            atomicAdd(&sm[NT + c + 1], q1);
        }
    }
    __syncthreads();
    if (tid < NT) {
        atomicAdd(&Sum[tid], (double)sm[tid]);
        atomicAdd(&Ss[tid],  (double)sm[NT + tid]);
    }
}

// ---------------------------------------------------------------------------
// BN finalize + final activation
// ---------------------------------------------------------------------------
__global__ void finalize_kernel(const double* __restrict__ Sum,
                                const double* __restrict__ Ss,
                                const float* __restrict__ gamma,
                                const float* __restrict__ beta,
                                float* __restrict__ sc, float* __restrict__ shf,
                                int C) {
    int c = threadIdx.x;
    if (c < C) {
        double mean = Sum[c] * (1.0 / (double)MM);
        double var  = Ss[c]  * (1.0 / (double)MM) - mean * mean;
        float s = gamma[c] * rsqrtf((float)var + BNEPS);
        sc[c]  = s;
        shf[c] = beta[c] - (float)mean * s;
    }
}

__global__ void act_kernel(float* __restrict__ Y,
                           const float* __restrict__ sc,
                           const float* __restrict__ shf) {
    int i = blockIdx.x * blockDim.x + threadIdx.x;
    float4 v = ((float4*)Y)[i];
    const float4 s4 = ((const float4*)sc)[i & 31];   // H1/4 = 32
    const float4 t4 = ((const float4*)shf)[i & 31];
    v.x = fmaxf(0.0f, fmaf(v.x, s4.x, t4.x));
    v.y = fmaxf(0.0f, fmaf(v.y, s4.y, t4.y));
    v.z = fmaxf(0.0f, fmaf(v.z, s4.z, t4.z));
    v.w = fmaxf(0.0f, fmaf(v.w, s4.w, t4.w));
    ((float4*)Y)[i] = v;
}

// ---------------------------------------------------------------------------
// Launch sequence
// ---------------------------------------------------------------------------
extern "C" void kernel_launch(void* const* d_in, const int* in_sizes, int n_in,
                              void* d_out, int out_size) {
    const float* xyz1    = (const float*)d_in[0];
    const float* xyz2    = (const float*)d_in[1];
    const float* points1 = (const float*)d_in[2];
    const float* points2 = (const float*)d_in[3];
    const float* rel_w   = (const float*)d_in[4];
    const float* rel_b   = (const float*)d_in[5];
    const float* W0      = (const float*)d_in[6];
    const float* b0      = (const float*)d_in[7];
    const float* g0      = (const float*)d_in[8];
    const float* be0     = (const float*)d_in[9];
    const float* W1      = (const float*)d_in[10];
    const float* b1      = (const float*)d_in[11];
    const float* g1      = (const float*)d_in[12];
    const float* be1     = (const float*)d_in[13];
    float* out = (float*)d_out;

    float *p_h, *p_y0, *p_w0t, *p_w1t, *p_s0, *p_t0, *p_s1, *p_t1;
    double *p_sum0, *p_ss0, *p_sum1, *p_ss1;
    cudaGetSymbolAddress((void**)&p_h,    g_h);
    cudaGetSymbolAddress((void**)&p_y0,   g_y0);
    cudaGetSymbolAddress((void**)&p_w0t,  g_w0t);
    cudaGetSymbolAddress((void**)&p_w1t,  g_w1t);
    cudaGetSymbolAddress((void**)&p_s0,   g_s0);
    cudaGetSymbolAddress((void**)&p_t0,   g_t0);
    cudaGetSymbolAddress((void**)&p_s1,   g_s1);
    cudaGetSymbolAddress((void**)&p_t1,   g_t1);
    cudaGetSymbolAddress((void**)&p_sum0, g_sum0);
    cudaGetSymbolAddress((void**)&p_ss0,  g_ss0);
    cudaGetSymbolAddress((void**)&p_sum1, g_sum1);
    cudaGetSymbolAddress((void**)&p_ss1,  g_ss1);

    const int smem0 = (128 + H0) * 36 * 4 * 2;    // 110592 B (2 stages)
    const int smem1 = 2 * 2 * 128 * 36 * 4;       // 73728 B
    cudaFuncSetAttribute(gemm0_kernel,
                         cudaFuncAttributeMaxDynamicSharedMemorySize, smem0);
    cudaFuncSetAttribute(gemm1_kernel,
                         cudaFuncAttributeMaxDynamicSharedMemorySize, smem1);

    zero_stats_kernel<<<1, 256>>>();
    convert_w_kernel<<<(H0 * K0 + 255) / 256, 256>>>(W0, W1);
    knn_kernel<<<dim3(NN / 256, BB), 128>>>(xyz1, xyz2, rel_w, rel_b);
    interp_kernel<<<MM / 4, 256>>>(points1, points2);

    // layer 0 (stats fused)
    gemm0_kernel<<<MM / 128, 512, smem0>>>(p_h, p_w0t, b0, p_y0, p_sum0, p_ss0);
    finalize_kernel<<<1, H0>>>(p_sum0, p_ss0, g0, be0, p_s0, p_t0, H0);

    // layer 1 (BN0+ReLU fused on A, stats fused on output)
    gemm1_kernel<<<MM / 128, 256, smem1>>>(p_y0, p_w1t, b1, p_s0, p_t0, out,
                                           p_sum1, p_ss1);
    finalize_kernel<<<1, H1>>>(p_sum1, p_ss1, g1, be1, p_s1, p_t1, H1);

    act_kernel<<<(MM * H1 / 4) / 256, 256>>>(out, p_s1, p_t1);
}

// round 8
// speedup vs baseline: 2.3247x; 1.0266x over previous
#include <cuda_runtime.h>
#include <math.h>
#include <stdint.h>

// Problem constants
#define BB   8
#define NN   8192
#define SS   2048
#define DD   256
#define MM   65536      // BB*NN
#define H0   256
#define H1   128
#define K0   512        // 2*DD
#define BNEPS 1e-5f

// ---------------------------------------------------------------------------
// Scratch
// ---------------------------------------------------------------------------
__device__ float  g_y0 [(size_t)MM * H0];   // layer0 pre-BN output (fp32)
__device__ float  g_w0t[H0 * K0];           // W0 as tf32 bits
__device__ float  g_w1t[H1 * H0];           // W1 as tf32 bits
__device__ int    g_idx[MM * 3];
__device__ float  g_w  [MM * 3];
__device__ double g_sum0[H0], g_ss0[H0], g_sum1[H1], g_ss1[H1];
__device__ float  g_s0[H0], g_t0[H0], g_s1[H1], g_t1[H1];

// ---------------------------------------------------------------------------
// Portable PTX helpers (toolchain targets sm_103 — no arch-accelerated instrs)
// ---------------------------------------------------------------------------
__device__ __forceinline__ uint32_t smem_u32(const void* p) {
    uint32_t a;
    asm("{ .reg .u64 t; cvta.to.shared.u64 t, %1; cvt.u32.u64 %0, t; }" : "=r"(a) : "l"(p));
    return a;
}

#define CP_ASYNC16(dst, src) \
    asm volatile("cp.async.cg.shared.global [%0], [%1], 16;" :: "r"(dst), "l"(src) : "memory")
#define CP_COMMIT() asm volatile("cp.async.commit_group;" ::: "memory")
#define CP_WAIT(n)  asm volatile("cp.async.wait_group %0;" :: "n"(n) : "memory")

__device__ __forceinline__ float f2tf32f(float x) {
    uint32_t r;
    asm("cvt.rna.tf32.f32 %0, %1;" : "=r"(r) : "f"(x));
    return __uint_as_float(r);
}

__device__ __forceinline__ void mma_tf32_16x8x8(float* c, const uint32_t* a,
                                                const uint32_t* b) {
    asm volatile(
        "mma.sync.aligned.m16n8k8.row.col.f32.tf32.tf32.f32 "
        "{%0,%1,%2,%3}, {%4,%5,%6,%7}, {%8,%9}, {%0,%1,%2,%3};"
        : "+f"(c[0]), "+f"(c[1]), "+f"(c[2]), "+f"(c[3])
        : "r"(a[0]), "r"(a[1]), "r"(a[2]), "r"(a[3]), "r"(b[0]), "r"(b[1]));
}

// ---------------------------------------------------------------------------
// Misc small kernels
// ---------------------------------------------------------------------------
__global__ void zero_stats_kernel() {
    int t = threadIdx.x;
    if (t < H0) { g_sum0[t] = 0.0; g_ss0[t] = 0.0; }
    if (t < H1) { g_sum1[t] = 0.0; g_ss1[t] = 0.0; }
}

__global__ void convert_w_kernel(const float* __restrict__ W0,
                                 const float* __restrict__ W1) {
    int i = blockIdx.x * blockDim.x + threadIdx.x;
    if (i < H0 * K0) g_w0t[i] = f2tf32f(W0[i]);
    if (i < H1 * H0) g_w1t[i] = f2tf32f(W1[i]);
}

// KNN: 128 threads/block, each thread handles 2 query points (tid, tid+128).
__global__ void knn_kernel(const float* __restrict__ xyz1,
                           const float* __restrict__ xyz2,
                           const float* __restrict__ rel_w,
                           const float* __restrict__ rel_b) {
    __shared__ float4 sh[SS];
    const int b = blockIdx.y;
    const float* x2 = xyz2 + (size_t)b * SS * 3;
    for (int s = threadIdx.x; s < SS; s += 128) {
        float x = x2[s * 3 + 0], y = x2[s * 3 + 1], z = x2[s * 3 + 2];
        sh[s] = make_float4(x, y, z, x * x + y * y + z * z);
    }
    __syncthreads();

    const int nA = blockIdx.x * 256 + threadIdx.x;
    const int gA = b * NN + nA;
    const int gB = gA + 128;

    const float ax = xyz1[(size_t)gA * 3 + 0];
    const float ay = xyz1[(size_t)gA * 3 + 1];
    const float az = xyz1[(size_t)gA * 3 + 2];
    const float an = ax * ax + ay * ay + az * az;
    const float bx = xyz1[(size_t)gB * 3 + 0];
    const float by = xyz1[(size_t)gB * 3 + 1];
    const float bz = xyz1[(size_t)gB * 3 + 2];
    const float bn = bx * bx + by * by + bz * bz;

    float ad0 = 3.4e38f, ad1 = 3.4e38f, ad2 = 3.4e38f;
    int   ai0 = 0, ai1 = 0, ai2 = 0;
    float bd0 = 3.4e38f, bd1 = 3.4e38f, bd2 = 3.4e38f;
    int   bi0 = 0, bi1 = 0, bi2 = 0;

    #pragma unroll 4
    for (int s = 0; s < SS; s++) {
        float4 p = sh[s];
        float da = (an + p.w) - 2.0f * (ax * p.x + ay * p.y + az * p.z);
        float db = (bn + p.w) - 2.0f * (bx * p.x + by * p.y + bz * p.z);
        if (da < ad2) {
            if (da < ad1) {
                ad2 = ad1; ai2 = ai1;
                if (da < ad0) { ad1 = ad0; ai1 = ai0; ad0 = da; ai0 = s; }
                else          { ad1 = da;  ai1 = s; }
            } else { ad2 = da; ai2 = s; }
        }
        if (db < bd2) {
            if (db < bd1) {
                bd2 = bd1; bi2 = bi1;
                if (db < bd0) { bd1 = bd0; bi1 = bi0; bd0 = db; bi0 = s; }
                else          { bd1 = db;  bi1 = s; }
            } else { bd2 = db; bi2 = s; }
        }
    }

    const float rw0 = rel_w[0], rw1 = rel_w[1], rw2 = rel_w[2], rw3 = rel_w[3];
    const float rb  = rel_b[0];
    {
        int   is[3] = { ai0, ai1, ai2 };
        float ds[3] = { ad0, ad1, ad2 };
        #pragma unroll
        for (int k = 0; k < 3; k++) {
            float4 p = sh[is[k]];
            float ox = ax - p.x, oy = ay - p.y, oz = az - p.z;
            float zl = ds[k] * rw0 + ox * rw1 + oy * rw2 + oz * rw3 + rb;
            float w = 1.0f / (1.0f + expf(-zl));
            g_idx[gA * 3 + k] = is[k];
            g_w[gA * 3 + k]   = w * (1.0f / 3.0f);
        }
    }
    {
        int   is[3] = { bi0, bi1, bi2 };
        float ds[3] = { bd0, bd1, bd2 };
        #pragma unroll
        for (int k = 0; k < 3; k++) {
            float4 p = sh[is[k]];
            float ox = bx - p.x, oy = by - p.y, oz = bz - p.z;
            float zl = ds[k] * rw0 + ox * rw1 + oy * rw2 + oz * rw3 + rb;
            float w = 1.0f / (1.0f + expf(-zl));
            g_idx[gB * 3 + k] = is[k];
            g_w[gB * 3 + k]   = w * (1.0f / 3.0f);
        }
    }
}

// ---------------------------------------------------------------------------
// GEMM0 with FUSED interp/concat on the A operand:
//   A[gn][k]   = tf32(points1[gn][k])                              k < 256
//   A[gn][k]   = tf32(fmaf(p2[j0], w0, fmaf(p2[j1], w1, p2[j2]*w2)))  k >= 256
//   y0 = A @ W0^T + b0, fused per-channel stats.
// Block tile 128x256 (full N), 512 threads, 16 warps 4Mx4N.
// A staged LDG->transform->STS; B via cp.async. One sync per chunk.
// A-staging map: 4 threads per row, 8 cols (2 float4) each.
// ---------------------------------------------------------------------------
__global__ __launch_bounds__(512)
void gemm0_kernel(const float* __restrict__ points1,
                  const float* __restrict__ points2,
                  const float* __restrict__ Bw,
                  const float* __restrict__ bias, float* __restrict__ C,
                  double* __restrict__ Sum, double* __restrict__ Ss) {
    constexpr int KT    = K0;             // 512
    constexpr int NT    = H0;             // 256
    constexpr int NC    = KT / 32;        // 16
    constexpr int LDT   = 36;
    constexpr int STAGE = (128 + NT) * LDT;

    extern __shared__ float sm[];
    const uint32_t smb = smem_u32(sm);

    const int tid    = threadIdx.x;
    const int wid    = tid >> 5;
    const int lane   = tid & 31;
    const int g      = lane >> 2;
    const int tg     = lane & 3;
    const int warp_m = wid >> 2;          // 0..3
    const int warp_n = wid & 3;           // 0..3
    const size_t bm  = (size_t)blockIdx.x * 128;

    // A staging: row lr (0..127), col group lq*8
    const int lr = tid >> 2;
    const int lq = tid & 3;
    const int gn = (int)bm + lr;
    const float* p2b = points2 + (size_t)(gn >> 13) * SS * DD;
    // per-row neighbors/weights (broadcast across the 4 threads of a row)
    const int   j0 = g_idx[gn * 3 + 0], j1 = g_idx[gn * 3 + 1], j2 = g_idx[gn * 3 + 2];
    const float w0 = g_w[gn * 3 + 0],  w1 = g_w[gn * 3 + 1],  w2 = g_w[gn * 3 + 2];
    const float* r0 = p2b + (size_t)j0 * DD;
    const float* r1 = p2b + (size_t)j1 * DD;
    const float* r2 = p2b + (size_t)j2 * DD;
    const float* q  = points1 + (size_t)gn * DD;

    float acc[2][8][4];
    #pragma unroll
    for (int mt = 0; mt < 2; mt++)
        #pragma unroll
        for (int nt = 0; nt < 8; nt++)
            #pragma unroll
            for (int i = 0; i < 4; i++) acc[mt][nt][i] = 0.0f;

    auto load_a_regs = [&](int kt, float4* av) {
        if (kt < 8) {                         // points1 columns
            const float* P = q + kt * 32 + lq * 8;
            av[0] = *(const float4*)P;
            av[1] = *(const float4*)(P + 4);
        } else {                              // interp columns
            const int cc = (kt - 8) * 32 + lq * 8;
            av[0] = *(const float4*)(r0 + cc);
            av[1] = *(const float4*)(r0 + cc + 4);
            av[2] = *(const float4*)(r1 + cc);
            av[3] = *(const float4*)(r1 + cc + 4);
            av[4] = *(const float4*)(r2 + cc);
            av[5] = *(const float4*)(r2 + cc + 4);
        }
    };
    auto store_a = [&](int kt, int s, const float4* av) {
        float* dst = sm + s * STAGE + lr * LDT + lq * 8;
        if (kt < 8) {
            #pragma unroll
            for (int i = 0; i < 2; i++) {
                float4 v;
                v.x = f2tf32f(av[i].x); v.y = f2tf32f(av[i].y);
                v.z = f2tf32f(av[i].z); v.w = f2tf32f(av[i].w);
                *(float4*)(dst + 4 * i) = v;
            }
        } else {
            #pragma unroll
            for (int i = 0; i < 2; i++) {
                float4 a = av[i], b = av[2 + i], c = av[4 + i];
                float4 v;
                v.x = f2tf32f(fmaf(a.x, w0, fmaf(b.x, w1, c.x * w2)));
                v.y = f2tf32f(fmaf(a.y, w0, fmaf(b.y, w1, c.y * w2)));
                v.z = f2tf32f(fmaf(a.z, w0, fmaf(b.z, w1, c.z * w2)));
                v.w = f2tf32f(fmaf(a.w, w0, fmaf(b.w, w1, c.w * w2)));
                *(float4*)(dst + 4 * i) = v;
            }
        }
    };
    auto load_b_stage = [&](int kt, int s) {
        const float* Bg = Bw + kt * 32;
        const uint32_t base = smb + (uint32_t)(s * STAGE + 128 * LDT) * 4u;
        #pragma unroll
        for (int i = 0; i < 4; i++) {         // B: 2048 float4
            int id = i * 512 + tid;
            int r = id >> 3, kk = (id & 7) * 4;
            CP_ASYNC16(base + (r * LDT + kk) * 4, Bg + (size_t)r * KT + kk);
        }
        CP_COMMIT();
    };

    // prologue: stage 0
    {
        float4 av[6];
        load_a_regs(0, av);
        load_b_stage(0, 0);
        store_a(0, 0, av);
    }

    for (int kt = 0; kt < NC; kt++) {
        CP_WAIT(0);          // B(kt) landed
        __syncthreads();     // stage kt (A STS + B) visible; buf (kt+1)&1 free

        float4 av[6];
        if (kt + 1 < NC) {
            load_a_regs(kt + 1, av);          // LDG overlaps compute(kt)
            load_b_stage(kt + 1, (kt + 1) & 1);
        }

        const uint32_t* as = (const uint32_t*)sm + (kt & 1) * STAGE + (warp_m * 32) * LDT;
        const uint32_t* bs = (const uint32_t*)sm + (kt & 1) * STAGE + 128 * LDT
                           + (warp_n * 64) * LDT;

        #pragma unroll
        for (int kc = 0; kc < 4; kc++) {
            uint32_t a[2][4];
            #pragma unroll
            for (int mt = 0; mt < 2; mt++) {
                int base = (mt * 16 + g) * LDT + kc * 8 + tg;
                a[mt][0] = as[base];
                a[mt][1] = as[base + 8 * LDT];
                a[mt][2] = as[base + 4];
                a[mt][3] = as[base + 8 * LDT + 4];
            }
            #pragma unroll
            for (int nt = 0; nt < 8; nt++) {
                uint32_t b[2];
                int bb = (nt * 8 + g) * LDT + kc * 8 + tg;
                b[0] = bs[bb];
                b[1] = bs[bb + 4];
                mma_tf32_16x8x8(acc[0][nt], a[0], b);
                mma_tf32_16x8x8(acc[1][nt], a[1], b);
            }
        }

        if (kt + 1 < NC) store_a(kt + 1, (kt + 1) & 1, av);
    }

    // smem reuse for per-channel stats partials
    __syncthreads();
    if (tid < NT) { sm[tid] = 0.0f; sm[NT + tid] = 0.0f; }
    __syncthreads();

    #pragma unroll
    for (int nt = 0; nt < 8; nt++) {
        int col = warp_n * 64 + nt * 8 + 2 * tg;
        float bi0 = __ldg(&bias[col]), bi1 = __ldg(&bias[col + 1]);
        float s0 = 0.f, s1 = 0.f, q0 = 0.f, q1 = 0.f;
        #pragma unroll
        for (int mt = 0; mt < 2; mt++) {
            size_t r = bm + warp_m * 32 + mt * 16 + g;
            float v0x = acc[mt][nt][0] + bi0, v0y = acc[mt][nt][1] + bi1;
            float v1x = acc[mt][nt][2] + bi0, v1y = acc[mt][nt][3] + bi1;
            *(float2*)(C + r * NT + col)       = make_float2(v0x, v0y);
            *(float2*)(C + (r + 8) * NT + col) = make_float2(v1x, v1y);
            s0 += v0x + v1x;  s1 += v0y + v1y;
            q0 += v0x * v0x + v1x * v1x;
            q1 += v0y * v0y + v1y * v1y;
        }
        #pragma unroll
        for (int d = 4; d < 32; d <<= 1) {
            s0 += __shfl_xor_sync(0xffffffffu, s0, d);
            s1 += __shfl_xor_sync(0xffffffffu, s1, d);
            q0 += __shfl_xor_sync(0xffffffffu, q0, d);
            q1 += __shfl_xor_sync(0xffffffffu, q1, d);
        }
        if (lane < 4) {
            int c = warp_n * 64 + nt * 8 + 2 * lane;
            atomicAdd(&sm[c],          s0);
            atomicAdd(&sm[c + 1],      s1);
            atomicAdd(&sm[NT + c],     q0);
            atomicAdd(&sm[NT + c + 1], q1);
        }
    }
    __syncthreads();
    if (tid < NT) {
        atomicAdd(&Sum[tid], (double)sm[tid]);
        atomicAdd(&Ss[tid],  (double)sm[NT + tid]);
    }
}

// ---------------------------------------------------------------------------
// GEMM1 with fused BN0+ReLU+tf32 on A and fused stats on the output:
//   out[M,128] = relu(s0*Y0 + t0) @ W1^T + b1
// ---------------------------------------------------------------------------
__global__ __launch_bounds__(256, 2)
void gemm1_kernel(const float* __restrict__ A, const float* __restrict__ Bw,
                  const float* __restrict__ bias,
                  const float* __restrict__ sc, const float* __restrict__ shf,
                  float* __restrict__ C,
                  double* __restrict__ Sum, double* __restrict__ Ss) {
    constexpr int KT    = H0;             // 256
    constexpr int NT    = H1;             // 128
    constexpr int NC    = KT / 32;        // 8
    constexpr int LDT   = 36;
    constexpr int STAGE = 2 * 128 * LDT;

    extern __shared__ float sm[];
    const uint32_t smb = smem_u32(sm);

    const int tid    = threadIdx.x;
    const int wid    = tid >> 5;
    const int lane   = tid & 31;
    const int g      = lane >> 2;
    const int tg     = lane & 3;
    const int warp_m = wid >> 1;
    const int warp_n = wid & 1;
    const size_t bm  = (size_t)blockIdx.x * 128;

    const int lr = tid >> 1;
    const int lk = (tid & 1) * 16;

    float acc[2][8][4];
    #pragma unroll
    for (int mt = 0; mt < 2; mt++)
        #pragma unroll
        for (int nt = 0; nt < 8; nt++)
            #pragma unroll
            for (int i = 0; i < 4; i++) acc[mt][nt][i] = 0.0f;

    auto load_a_regs = [&](int kt, float4* av) {
        const float* Ag = A + (size_t)(bm + lr) * KT + kt * 32 + lk;
        #pragma unroll
        for (int i = 0; i < 4; i++) av[i] = *(const float4*)(Ag + 4 * i);
    };
    auto store_a = [&](int kt, int s, const float4* av) {
        const int c0 = kt * 32 + lk;
        float* dst = sm + s * STAGE + lr * LDT + lk;
        #pragma unroll
        for (int i = 0; i < 4; i++) {
            float4 s4 = *(const float4*)(sc  + c0 + 4 * i);
            float4 t4 = *(const float4*)(shf + c0 + 4 * i);
            float4 v;
            v.x = f2tf32f(fmaxf(0.0f, fmaf(av[i].x, s4.x, t4.x)));
            v.y = f2tf32f(fmaxf(0.0f, fmaf(av[i].y, s4.y, t4.y)));
            v.z = f2tf32f(fmaxf(0.0f, fmaf(av[i].z, s4.z, t4.z)));
            v.w = f2tf32f(fmaxf(0.0f, fmaf(av[i].w, s4.w, t4.w)));
            *(float4*)(dst + 4 * i) = v;
        }
    };
    auto load_b_stage = [&](int kt, int s) {
        const float* Bg = Bw + kt * 32;
        const uint32_t base = smb + (uint32_t)(s * STAGE + 128 * LDT) * 4u;
        #pragma unroll
        for (int i = 0; i < 4; i++) {
            int id = i * 256 + tid;
            int r = id >> 3, kk = (id & 7) * 4;
            CP_ASYNC16(base + (r * LDT + kk) * 4, Bg + (size_t)r * KT + kk);
        }
        CP_COMMIT();
    };

    {
        float4 av[4];
        load_a_regs(0, av);
        load_b_stage(0, 0);
        store_a(0, 0, av);
    }

    for (int kt = 0; kt < NC; kt++) {
        CP_WAIT(0);
        __syncthreads();

        float4 av[4];
        if (kt + 1 < NC) {
            load_a_regs(kt + 1, av);
            load_b_stage(kt + 1, (kt + 1) & 1);
        }

        const uint32_t* as = (const uint32_t*)sm + (kt & 1) * STAGE + (warp_m * 32) * LDT;
        const uint32_t* bs = (const uint32_t*)sm + (kt & 1) * STAGE + 128 * LDT
                           + (warp_n * 64) * LDT;

        #pragma unroll
        for (int kc = 0; kc < 4; kc++) {
            uint32_t a[2][4];
            #pragma unroll
            for (int mt = 0; mt < 2; mt++) {
                int base = (mt * 16 + g) * LDT + kc * 8 + tg;
                a[mt][0] = as[base];
                a[mt][1] = as[base + 8 * LDT];
                a[mt][2] = as[base + 4];
                a[mt][3] = as[base + 8 * LDT + 4];
            }
            #pragma unroll
            for (int nt = 0; nt < 8; nt++) {
                uint32_t b[2];
                int bb = (nt * 8 + g) * LDT + kc * 8 + tg;
                b[0] = bs[bb];
                b[1] = bs[bb + 4];
                mma_tf32_16x8x8(acc[0][nt], a[0], b);
                mma_tf32_16x8x8(acc[1][nt], a[1], b);
            }
        }

        if (kt + 1 < NC) store_a(kt + 1, (kt + 1) & 1, av);
    }

    __syncthreads();
    if (tid < NT) { sm[tid] = 0.0f; sm[NT + tid] = 0.0f; }
    __syncthreads();

    #pragma unroll
    for (int nt = 0; nt < 8; nt++) {
        int col = warp_n * 64 + nt * 8 + 2 * tg;
        float bi0 = __ldg(&bias[col]), bi1 = __ldg(&bias[col + 1]);
        float s0 = 0.f, s1 = 0.f, q0 = 0.f, q1 = 0.f;
        #pragma unroll
        for (int mt = 0; mt < 2; mt++) {
            size_t r = bm + warp_m * 32 + mt * 16 + g;
            float v0x = acc[mt][nt][0] + bi0, v0y = acc[mt][nt][1] + bi1;
            float v1x = acc[mt][nt][2] + bi0, v1y = acc[mt][nt][3] + bi1;
            *(float2*)(C + r * NT + col)       = make_float2(v0x, v0y);
            *(float2*)(C + (r + 8) * NT + col) = make_float2(v1x, v1y);
            s0 += v0x + v1x;  s1 += v0y + v1y;
            q0 += v0x * v0x + v1x * v1x;
            q1 += v0y * v0y + v1y * v1y;
        }
        #pragma unroll
        for (int d = 4; d < 32; d <<= 1) {
            s0 += __shfl_xor_sync(0xffffffffu, s0, d);
            s1 += __shfl_xor_sync(0xffffffffu, s1, d);
            q0 += __shfl_xor_sync(0xffffffffu, q0, d);
            q1 += __shfl_xor_sync(0xffffffffu, q1, d);
        }
        if (lane < 4) {
            int c = warp_n * 64 + nt * 8 + 2 * lane;
            atomicAdd(&sm[c],          s0);
            atomicAdd(&sm[c + 1],      s1);
            atomicAdd(&sm[NT + c],     q0);
            atomicAdd(&sm[NT + c + 1], q1);
        }
    }
    __syncthreads();
    if (tid < NT) {
        atomicAdd(&Sum[tid], (double)sm[tid]);
        atomicAdd(&Ss[tid],  (double)sm[NT + tid]);
    }
}

// ---------------------------------------------------------------------------
// BN finalize + final activation
// ---------------------------------------------------------------------------
__global__ void finalize_kernel(const double* __restrict__ Sum,
                                const double* __restrict__ Ss,
                                const float* __restrict__ gamma,
                                const float* __restrict__ beta,
                                float* __restrict__ sc, float* __restrict__ shf,
                                int C) {
    int c = threadIdx.x;
    if (c < C) {
        double mean = Sum[c] * (1.0 / (double)MM);
        double var  = Ss[c]  * (1.0 / (double)MM) - mean * mean;
        float s = gamma[c] * rsqrtf((float)var + BNEPS);
        sc[c]  = s;
        shf[c] = beta[c] - (float)mean * s;
    }
}

__global__ void act_kernel(float* __restrict__ Y,
                           const float* __restrict__ sc,
                           const float* __restrict__ shf) {
    int i = blockIdx.x * blockDim.x + threadIdx.x;
    float4 v = ((float4*)Y)[i];
    const float4 s4 = ((const float4*)sc)[i & 31];   // H1/4 = 32
    const float4 t4 = ((const float4*)shf)[i & 31];
    v.x = fmaxf(0.0f, fmaf(v.x, s4.x, t4.x));
    v.y = fmaxf(0.0f, fmaf(v.y, s4.y, t4.y));
    v.z = fmaxf(0.0f, fmaf(v.z, s4.z, t4.z));
    v.w = fmaxf(0.0f, fmaf(v.w, s4.w, t4.w));
    ((float4*)Y)[i] = v;
}

// ---------------------------------------------------------------------------
// Launch sequence
// ---------------------------------------------------------------------------
extern "C" void kernel_launch(void* const* d_in, const int* in_sizes, int n_in,
                              void* d_out, int out_size) {
    const float* xyz1    = (const float*)d_in[0];
    const float* xyz2    = (const float*)d_in[1];
    const float* points1 = (const float*)d_in[2];
    const float* points2 = (const float*)d_in[3];
    const float* rel_w   = (const float*)d_in[4];
    const float* rel_b   = (const float*)d_in[5];
    const float* W0      = (const float*)d_in[6];
    const float* b0      = (const float*)d_in[7];
    const float* g0      = (const float*)d_in[8];
    const float* be0     = (const float*)d_in[9];
    const float* W1      = (const float*)d_in[10];
    const float* b1      = (const float*)d_in[11];
    const float* g1      = (const float*)d_in[12];
    const float* be1     = (const float*)d_in[13];
    float* out = (float*)d_out;

    float *p_y0, *p_w0t, *p_w1t, *p_s0, *p_t0, *p_s1, *p_t1;
    double *p_sum0, *p_ss0, *p_sum1, *p_ss1;
    cudaGetSymbolAddress((void**)&p_y0,   g_y0);
    cudaGetSymbolAddress((void**)&p_w0t,  g_w0t);
    cudaGetSymbolAddress((void**)&p_w1t,  g_w1t);
    cudaGetSymbolAddress((void**)&p_s0,   g_s0);
    cudaGetSymbolAddress((void**)&p_t0,   g_t0);
    cudaGetSymbolAddress((void**)&p_s1,   g_s1);
    cudaGetSymbolAddress((void**)&p_t1,   g_t1);
    cudaGetSymbolAddress((void**)&p_sum0, g_sum0);
    cudaGetSymbolAddress((void**)&p_ss0,  g_ss0);
    cudaGetSymbolAddress((void**)&p_sum1, g_sum1);
    cudaGetSymbolAddress((void**)&p_ss1,  g_ss1);

    const int smem0 = (128 + H0) * 36 * 4 * 2;    // 110592 B
    const int smem1 = 2 * 2 * 128 * 36 * 4;       // 73728 B
    cudaFuncSetAttribute(gemm0_kernel,
                         cudaFuncAttributeMaxDynamicSharedMemorySize, smem0);
    cudaFuncSetAttribute(gemm1_kernel,
                         cudaFuncAttributeMaxDynamicSharedMemorySize, smem1);

    zero_stats_kernel<<<1, 256>>>();
    convert_w_kernel<<<(H0 * K0 + 255) / 256, 256>>>(W0, W1);
    knn_kernel<<<dim3(NN / 256, BB), 128>>>(xyz1, xyz2, rel_w, rel_b);

    // layer 0 (interp + concat + stats fused)
    gemm0_kernel<<<MM / 128, 512, smem0>>>(points1, points2, p_w0t, b0,
                                           p_y0, p_sum0, p_ss0);
    finalize_kernel<<<1, H0>>>(p_sum0, p_ss0, g0, be0, p_s0, p_t0, H0);

    // layer 1 (BN0+ReLU fused on A, stats fused on output)
    gemm1_kernel<<<MM / 128, 256, smem1>>>(p_y0, p_w1t, b1, p_s0, p_t0, out,
                                           p_sum1, p_ss1);
    finalize_kernel<<<1, H1>>>(p_sum1, p_ss1, g1, be1, p_s1, p_t1, H1);

    act_kernel<<<(MM * H1 / 4) / 256, 256>>>(out, p_s1, p_t1);
}

// round 9
// speedup vs baseline: 2.4522x; 1.0549x over previous
#include <cuda_runtime.h>
#include <math.h>
#include <stdint.h>

// Problem constants
#define BB   8
#define NN   8192
#define SS   2048
#define DD   256
#define MM   65536      // BB*NN
#define H0   256
#define H1   128
#define K0   512        // 2*DD
#define BNEPS 1e-5f

// ---------------------------------------------------------------------------
// Scratch
// ---------------------------------------------------------------------------
__device__ float  g_y0 [(size_t)MM * H0];   // layer0 pre-BN output (fp32)
__device__ float  g_w0t[H0 * K0];           // W0 as tf32 bits
__device__ float  g_w1t[H1 * H0];           // W1 as tf32 bits
__device__ int    g_idx[MM * 3];
__device__ float  g_w  [MM * 3];
__device__ double g_sum0[H0], g_ss0[H0], g_sum1[H1], g_ss1[H1];
__device__ float  g_s0[H0], g_t0[H0], g_s1[H1], g_t1[H1];

// ---------------------------------------------------------------------------
// Portable PTX helpers (toolchain targets sm_103 — no arch-accelerated instrs)
// ---------------------------------------------------------------------------
__device__ __forceinline__ uint32_t smem_u32(const void* p) {
    uint32_t a;
    asm("{ .reg .u64 t; cvta.to.shared.u64 t, %1; cvt.u32.u64 %0, t; }" : "=r"(a) : "l"(p));
    return a;
}

#define CP_ASYNC16(dst, src) \
    asm volatile("cp.async.cg.shared.global [%0], [%1], 16;" :: "r"(dst), "l"(src) : "memory")
#define CP_COMMIT() asm volatile("cp.async.commit_group;" ::: "memory")
#define CP_WAIT(n)  asm volatile("cp.async.wait_group %0;" :: "n"(n) : "memory")

__device__ __forceinline__ float f2tf32f(float x) {
    uint32_t r;
    asm("cvt.rna.tf32.f32 %0, %1;" : "=r"(r) : "f"(x));
    return __uint_as_float(r);
}

__device__ __forceinline__ void mma_tf32_16x8x8(float* c, const uint32_t* a,
                                                const uint32_t* b) {
    asm volatile(
        "mma.sync.aligned.m16n8k8.row.col.f32.tf32.tf32.f32 "
        "{%0,%1,%2,%3}, {%4,%5,%6,%7}, {%8,%9}, {%0,%1,%2,%3};"
        : "+f"(c[0]), "+f"(c[1]), "+f"(c[2]), "+f"(c[3])
        : "r"(a[0]), "r"(a[1]), "r"(a[2]), "r"(a[3]), "r"(b[0]), "r"(b[1]));
}

// ---------------------------------------------------------------------------
// Misc small kernels
// ---------------------------------------------------------------------------
__global__ void zero_stats_kernel() {
    int t = threadIdx.x;
    if (t < H0) { g_sum0[t] = 0.0; g_ss0[t] = 0.0; }
    if (t < H1) { g_sum1[t] = 0.0; g_ss1[t] = 0.0; }
}

__global__ void convert_w_kernel(const float* __restrict__ W0,
                                 const float* __restrict__ W1) {
    int i = blockIdx.x * blockDim.x + threadIdx.x;
    if (i < H0 * K0) g_w0t[i] = f2tf32f(W0[i]);
    if (i < H1 * H0) g_w1t[i] = f2tf32f(W1[i]);
}

// KNN: 128 threads/block, each thread handles 2 query points (tid, tid+128).
__global__ void knn_kernel(const float* __restrict__ xyz1,
                           const float* __restrict__ xyz2,
                           const float* __restrict__ rel_w,
                           const float* __restrict__ rel_b) {
    __shared__ float4 sh[SS];
    const int b = blockIdx.y;
    const float* x2 = xyz2 + (size_t)b * SS * 3;
    for (int s = threadIdx.x; s < SS; s += 128) {
        float x = x2[s * 3 + 0], y = x2[s * 3 + 1], z = x2[s * 3 + 2];
        sh[s] = make_float4(x, y, z, x * x + y * y + z * z);
    }
    __syncthreads();

    const int nA = blockIdx.x * 256 + threadIdx.x;
    const int gA = b * NN + nA;
    const int gB = gA + 128;

    const float ax = xyz1[(size_t)gA * 3 + 0];
    const float ay = xyz1[(size_t)gA * 3 + 1];
    const float az = xyz1[(size_t)gA * 3 + 2];
    const float an = ax * ax + ay * ay + az * az;
    const float bx = xyz1[(size_t)gB * 3 + 0];
    const float by = xyz1[(size_t)gB * 3 + 1];
    const float bz = xyz1[(size_t)gB * 3 + 2];
    const float bn = bx * bx + by * by + bz * bz;

    float ad0 = 3.4e38f, ad1 = 3.4e38f, ad2 = 3.4e38f;
    int   ai0 = 0, ai1 = 0, ai2 = 0;
    float bd0 = 3.4e38f, bd1 = 3.4e38f, bd2 = 3.4e38f;
    int   bi0 = 0, bi1 = 0, bi2 = 0;

    #pragma unroll 4
    for (int s = 0; s < SS; s++) {
        float4 p = sh[s];
        float da = (an + p.w) - 2.0f * (ax * p.x + ay * p.y + az * p.z);
        float db = (bn + p.w) - 2.0f * (bx * p.x + by * p.y + bz * p.z);
        if (da < ad2) {
            if (da < ad1) {
                ad2 = ad1; ai2 = ai1;
                if (da < ad0) { ad1 = ad0; ai1 = ai0; ad0 = da; ai0 = s; }
                else          { ad1 = da;  ai1 = s; }
            } else { ad2 = da; ai2 = s; }
        }
        if (db < bd2) {
            if (db < bd1) {
                bd2 = bd1; bi2 = bi1;
                if (db < bd0) { bd1 = bd0; bi1 = bi0; bd0 = db; bi0 = s; }
                else          { bd1 = db;  bi1 = s; }
            } else { bd2 = db; bi2 = s; }
        }
    }

    const float rw0 = rel_w[0], rw1 = rel_w[1], rw2 = rel_w[2], rw3 = rel_w[3];
    const float rb  = rel_b[0];
    {
        int   is[3] = { ai0, ai1, ai2 };
        float ds[3] = { ad0, ad1, ad2 };
        #pragma unroll
        for (int k = 0; k < 3; k++) {
            float4 p = sh[is[k]];
            float ox = ax - p.x, oy = ay - p.y, oz = az - p.z;
            float zl = ds[k] * rw0 + ox * rw1 + oy * rw2 + oz * rw3 + rb;
            float w = 1.0f / (1.0f + expf(-zl));
            g_idx[gA * 3 + k] = is[k];
            g_w[gA * 3 + k]   = w * (1.0f / 3.0f);
        }
    }
    {
        int   is[3] = { bi0, bi1, bi2 };
        float ds[3] = { bd0, bd1, bd2 };
        #pragma unroll
        for (int k = 0; k < 3; k++) {
            float4 p = sh[is[k]];
            float ox = bx - p.x, oy = by - p.y, oz = bz - p.z;
            float zl = ds[k] * rw0 + ox * rw1 + oy * rw2 + oz * rw3 + rb;
            float w = 1.0f / (1.0f + expf(-zl));
            g_idx[gB * 3 + k] = is[k];
            g_w[gB * 3 + k]   = w * (1.0f / 3.0f);
        }
    }
}

// ---------------------------------------------------------------------------
// GEMM0 with FUSED interp/concat on the A operand.
// Block tile 64x256 (full N), 256 threads, 8 warps 2Mx4N, warp tile 32x64.
// 2 CTAs/SM so cross-CTA overlap hides the gather-LDG latency.
// A staged LDG->transform->STS (4 threads/row, 8 cols each); B via cp.async.
// ---------------------------------------------------------------------------
__global__ __launch_bounds__(256, 2)
void gemm0_kernel(const float* __restrict__ points1,
                  const float* __restrict__ points2,
                  const float* __restrict__ Bw,
                  const float* __restrict__ bias, float* __restrict__ C,
                  double* __restrict__ Sum, double* __restrict__ Ss) {
    constexpr int KT    = K0;             // 512
    constexpr int NT    = H0;             // 256
    constexpr int TM    = 64;             // M tile
    constexpr int NC    = KT / 32;        // 16
    constexpr int LDT   = 36;
    constexpr int STAGE = (TM + NT) * LDT;

    extern __shared__ float sm[];
    const uint32_t smb = smem_u32(sm);

    const int tid    = threadIdx.x;
    const int wid    = tid >> 5;
    const int lane   = tid & 31;
    const int g      = lane >> 2;
    const int tg     = lane & 3;
    const int warp_m = wid >> 2;          // 0..1
    const int warp_n = wid & 3;           // 0..3
    const size_t bm  = (size_t)blockIdx.x * TM;

    // A staging: row lr (0..63), col group lq*8
    const int lr = tid >> 2;
    const int lq = tid & 3;
    const int gn = (int)bm + lr;
    const float* p2b = points2 + (size_t)(gn >> 13) * SS * DD;
    const int   j0 = g_idx[gn * 3 + 0], j1 = g_idx[gn * 3 + 1], j2 = g_idx[gn * 3 + 2];
    const float w0 = g_w[gn * 3 + 0],  w1 = g_w[gn * 3 + 1],  w2 = g_w[gn * 3 + 2];
    const float* r0 = p2b + (size_t)j0 * DD;
    const float* r1 = p2b + (size_t)j1 * DD;
    const float* r2 = p2b + (size_t)j2 * DD;
    const float* q  = points1 + (size_t)gn * DD;

    float acc[2][8][4];
    #pragma unroll
    for (int mt = 0; mt < 2; mt++)
        #pragma unroll
        for (int nt = 0; nt < 8; nt++)
            #pragma unroll
            for (int i = 0; i < 4; i++) acc[mt][nt][i] = 0.0f;

    auto load_a_regs = [&](int kt, float4* av) {
        if (kt < 8) {                         // points1 columns
            const float* P = q + kt * 32 + lq * 8;
            av[0] = *(const float4*)P;
            av[1] = *(const float4*)(P + 4);
        } else {                              // interp columns
            const int cc = (kt - 8) * 32 + lq * 8;
            av[0] = *(const float4*)(r0 + cc);
            av[1] = *(const float4*)(r0 + cc + 4);
            av[2] = *(const float4*)(r1 + cc);
            av[3] = *(const float4*)(r1 + cc + 4);
            av[4] = *(const float4*)(r2 + cc);
            av[5] = *(const float4*)(r2 + cc + 4);
        }
    };
    auto store_a = [&](int kt, int s, const float4* av) {
        float* dst = sm + s * STAGE + lr * LDT + lq * 8;
        if (kt < 8) {
            #pragma unroll
            for (int i = 0; i < 2; i++) {
                float4 v;
                v.x = f2tf32f(av[i].x); v.y = f2tf32f(av[i].y);
                v.z = f2tf32f(av[i].z); v.w = f2tf32f(av[i].w);
                *(float4*)(dst + 4 * i) = v;
            }
        } else {
            #pragma unroll
            for (int i = 0; i < 2; i++) {
                float4 a = av[i], b = av[2 + i], c = av[4 + i];
                float4 v;
                v.x = f2tf32f(fmaf(a.x, w0, fmaf(b.x, w1, c.x * w2)));
                v.y = f2tf32f(fmaf(a.y, w0, fmaf(b.y, w1, c.y * w2)));
                v.z = f2tf32f(fmaf(a.z, w0, fmaf(b.z, w1, c.z * w2)));
                v.w = f2tf32f(fmaf(a.w, w0, fmaf(b.w, w1, c.w * w2)));
                *(float4*)(dst + 4 * i) = v;
            }
        }
    };
    auto load_b_stage = [&](int kt, int s) {
        const float* Bg = Bw + kt * 32;
        const uint32_t base = smb + (uint32_t)(s * STAGE + TM * LDT) * 4u;
        #pragma unroll
        for (int i = 0; i < 8; i++) {         // B: 2048 float4, 256 threads
            int id = i * 256 + tid;
            int r = id >> 3, kk = (id & 7) * 4;
            CP_ASYNC16(base + (r * LDT + kk) * 4, Bg + (size_t)r * KT + kk);
        }
        CP_COMMIT();
    };

    // prologue: stage 0
    {
        float4 av[6];
        load_a_regs(0, av);
        load_b_stage(0, 0);
        store_a(0, 0, av);
    }

    for (int kt = 0; kt < NC; kt++) {
        CP_WAIT(0);          // B(kt) landed
        __syncthreads();     // stage kt visible; buf (kt+1)&1 free

        float4 av[6];
        if (kt + 1 < NC) {
            load_a_regs(kt + 1, av);          // LDG overlaps compute(kt)
            load_b_stage(kt + 1, (kt + 1) & 1);
        }

        const uint32_t* as = (const uint32_t*)sm + (kt & 1) * STAGE + (warp_m * 32) * LDT;
        const uint32_t* bs = (const uint32_t*)sm + (kt & 1) * STAGE + TM * LDT
                           + (warp_n * 64) * LDT;

        #pragma unroll
        for (int kc = 0; kc < 4; kc++) {
            uint32_t a[2][4];
            #pragma unroll
            for (int mt = 0; mt < 2; mt++) {
                int base = (mt * 16 + g) * LDT + kc * 8 + tg;
                a[mt][0] = as[base];
                a[mt][1] = as[base + 8 * LDT];
                a[mt][2] = as[base + 4];
                a[mt][3] = as[base + 8 * LDT + 4];
            }
            #pragma unroll
            for (int nt = 0; nt < 8; nt++) {
                uint32_t b[2];
                int bb = (nt * 8 + g) * LDT + kc * 8 + tg;
                b[0] = bs[bb];
                b[1] = bs[bb + 4];
                mma_tf32_16x8x8(acc[0][nt], a[0], b);
                mma_tf32_16x8x8(acc[1][nt], a[1], b);
            }
        }

        if (kt + 1 < NC) store_a(kt + 1, (kt + 1) & 1, av);
    }

    // smem reuse for per-channel stats partials
    __syncthreads();
    if (tid < NT) { sm[tid] = 0.0f; sm[NT + tid] = 0.0f; }
    __syncthreads();

    #pragma unroll
    for (int nt = 0; nt < 8; nt++) {
        int col = warp_n * 64 + nt * 8 + 2 * tg;
        float bi0 = __ldg(&bias[col]), bi1 = __ldg(&bias[col + 1]);
        float s0 = 0.f, s1 = 0.f, q0 = 0.f, q1 = 0.f;
        #pragma unroll
        for (int mt = 0; mt < 2; mt++) {
            size_t r = bm + warp_m * 32 + mt * 16 + g;
            float v0x = acc[mt][nt][0] + bi0, v0y = acc[mt][nt][1] + bi1;
            float v1x = acc[mt][nt][2] + bi0, v1y = acc[mt][nt][3] + bi1;
            *(float2*)(C + r * NT + col)       = make_float2(v0x, v0y);
            *(float2*)(C + (r + 8) * NT + col) = make_float2(v1x, v1y);
            s0 += v0x + v1x;  s1 += v0y + v1y;
            q0 += v0x * v0x + v1x * v1x;
            q1 += v0y * v0y + v1y * v1y;
        }
        #pragma unroll
        for (int d = 4; d < 32; d <<= 1) {
            s0 += __shfl_xor_sync(0xffffffffu, s0, d);
            s1 += __shfl_xor_sync(0xffffffffu, s1, d);
            q0 += __shfl_xor_sync(0xffffffffu, q0, d);
            q1 += __shfl_xor_sync(0xffffffffu, q1, d);
        }
        if (lane < 4) {
            int c = warp_n * 64 + nt * 8 + 2 * lane;
            atomicAdd(&sm[c],          s0);
            atomicAdd(&sm[c + 1],      s1);
            atomicAdd(&sm[NT + c],     q0);
            atomicAdd(&sm[NT + c + 1], q1);
        }
    }
    __syncthreads();
    if (tid < NT) {
        atomicAdd(&Sum[tid], (double)sm[tid]);
        atomicAdd(&Ss[tid],  (double)sm[NT + tid]);
    }
}

// ---------------------------------------------------------------------------
// GEMM1 with fused BN0+ReLU+tf32 on A and fused stats on the output:
//   out[M,128] = relu(s0*Y0 + t0) @ W1^T + b1
// ---------------------------------------------------------------------------
__global__ __launch_bounds__(256, 2)
void gemm1_kernel(const float* __restrict__ A, const float* __restrict__ Bw,
                  const float* __restrict__ bias,
                  const float* __restrict__ sc, const float* __restrict__ shf,
                  float* __restrict__ C,
                  double* __restrict__ Sum, double* __restrict__ Ss) {
    constexpr int KT    = H0;             // 256
    constexpr int NT    = H1;             // 128
    constexpr int NC    = KT / 32;        // 8
    constexpr int LDT   = 36;
    constexpr int STAGE = 2 * 128 * LDT;

    extern __shared__ float sm[];
    const uint32_t smb = smem_u32(sm);

    const int tid    = threadIdx.x;
    const int wid    = tid >> 5;
    const int lane   = tid & 31;
    const int g      = lane >> 2;
    const int tg     = lane & 3;
    const int warp_m = wid >> 1;
    const int warp_n = wid & 1;
    const size_t bm  = (size_t)blockIdx.x * 128;

    const int lr = tid >> 1;
    const int lk = (tid & 1) * 16;

    float acc[2][8][4];
    #pragma unroll
    for (int mt = 0; mt < 2; mt++)
        #pragma unroll
        for (int nt = 0; nt < 8; nt++)
            #pragma unroll
            for (int i = 0; i < 4; i++) acc[mt][nt][i] = 0.0f;

    auto load_a_regs = [&](int kt, float4* av) {
        const float* Ag = A + (size_t)(bm + lr) * KT + kt * 32 + lk;
        #pragma unroll
        for (int i = 0; i < 4; i++) av[i] = *(const float4*)(Ag + 4 * i);
    };
    auto store_a = [&](int kt, int s, const float4* av) {
        const int c0 = kt * 32 + lk;
        float* dst = sm + s * STAGE + lr * LDT + lk;
        #pragma unroll
        for (int i = 0; i < 4; i++) {
            float4 s4 = *(const float4*)(sc  + c0 + 4 * i);
            float4 t4 = *(const float4*)(shf + c0 + 4 * i);
            float4 v;
            v.x = f2tf32f(fmaxf(0.0f, fmaf(av[i].x, s4.x, t4.x)));
            v.y = f2tf32f(fmaxf(0.0f, fmaf(av[i].y, s4.y, t4.y)));
            v.z = f2tf32f(fmaxf(0.0f, fmaf(av[i].z, s4.z, t4.z)));
            v.w = f2tf32f(fmaxf(0.0f, fmaf(av[i].w, s4.w, t4.w)));
            *(float4*)(dst + 4 * i) = v;
        }
    };
    auto load_b_stage = [&](int kt, int s) {
        const float* Bg = Bw + kt * 32;
        const uint32_t base = smb + (uint32_t)(s * STAGE + 128 * LDT) * 4u;
        #pragma unroll
        for (int i = 0; i < 4; i++) {
            int id = i * 256 + tid;
            int r = id >> 3, kk = (id & 7) * 4;
            CP_ASYNC16(base + (r * LDT + kk) * 4, Bg + (size_t)r * KT + kk);
        }
        CP_COMMIT();
    };

    {
        float4 av[4];
        load_a_regs(0, av);
        load_b_stage(0, 0);
        store_a(0, 0, av);
    }

    for (int kt = 0; kt < NC; kt++) {
        CP_WAIT(0);
        __syncthreads();

        float4 av[4];
        if (kt + 1 < NC) {
            load_a_regs(kt + 1, av);
            load_b_stage(kt + 1, (kt + 1) & 1);
        }

        const uint32_t* as = (const uint32_t*)sm + (kt & 1) * STAGE + (warp_m * 32) * LDT;
        const uint32_t* bs = (const uint32_t*)sm + (kt & 1) * STAGE + 128 * LDT
                           + (warp_n * 64) * LDT;

        #pragma unroll
        for (int kc = 0; kc < 4; kc++) {
            uint32_t a[2][4];
            #pragma unroll
            for (int mt = 0; mt < 2; mt++) {
                int base = (mt * 16 + g) * LDT + kc * 8 + tg;
                a[mt][0] = as[base];
                a[mt][1] = as[base + 8 * LDT];
                a[mt][2] = as[base + 4];
                a[mt][3] = as[base + 8 * LDT + 4];
            }
            #pragma unroll
            for (int nt = 0; nt < 8; nt++) {
                uint32_t b[2];
                int bb = (nt * 8 + g) * LDT + kc * 8 + tg;
                b[0] = bs[bb];
                b[1] = bs[bb + 4];
                mma_tf32_16x8x8(acc[0][nt], a[0], b);
                mma_tf32_16x8x8(acc[1][nt], a[1], b);
            }
        }

        if (kt + 1 < NC) store_a(kt + 1, (kt + 1) & 1, av);
    }

    __syncthreads();
    if (tid < NT) { sm[tid] = 0.0f; sm[NT + tid] = 0.0f; }
    __syncthreads();

    #pragma unroll
    for (int nt = 0; nt < 8; nt++) {
        int col = warp_n * 64 + nt * 8 + 2 * tg;
        float bi0 = __ldg(&bias[col]), bi1 = __ldg(&bias[col + 1]);
        float s0 = 0.f, s1 = 0.f, q0 = 0.f, q1 = 0.f;
        #pragma unroll
        for (int mt = 0; mt < 2; mt++) {
            size_t r = bm + warp_m * 32 + mt * 16 + g;
            float v0x = acc[mt][nt][0] + bi0, v0y = acc[mt][nt][1] + bi1;
            float v1x = acc[mt][nt][2] + bi0, v1y = acc[mt][nt][3] + bi1;
            *(float2*)(C + r * NT + col)       = make_float2(v0x, v0y);
            *(float2*)(C + (r + 8) * NT + col) = make_float2(v1x, v1y);
            s0 += v0x + v1x;  s1 += v0y + v1y;
            q0 += v0x * v0x + v1x * v1x;
            q1 += v0y * v0y + v1y * v1y;
        }
        #pragma unroll
        for (int d = 4; d < 32; d <<= 1) {
            s0 += __shfl_xor_sync(0xffffffffu, s0, d);
            s1 += __shfl_xor_sync(0xffffffffu, s1, d);
            q0 += __shfl_xor_sync(0xffffffffu, q0, d);
            q1 += __shfl_xor_sync(0xffffffffu, q1, d);
        }
        if (lane < 4) {
            int c = warp_n * 64 + nt * 8 + 2 * lane;
            atomicAdd(&sm[c],          s0);
            atomicAdd(&sm[c + 1],      s1);
            atomicAdd(&sm[NT + c],     q0);
            atomicAdd(&sm[NT + c + 1], q1);
        }
    }
    __syncthreads();
    if (tid < NT) {
        atomicAdd(&Sum[tid], (double)sm[tid]);
        atomicAdd(&Ss[tid],  (double)sm[NT + tid]);
    }
}

// ---------------------------------------------------------------------------
// BN finalize + final activation
// ---------------------------------------------------------------------------
__global__ void finalize_kernel(const double* __restrict__ Sum,
                                const double* __restrict__ Ss,
                                const float* __restrict__ gamma,
                                const float* __restrict__ beta,
                                float* __restrict__ sc, float* __restrict__ shf,
                                int C) {
    int c = threadIdx.x;
    if (c < C) {
        double mean = Sum[c] * (1.0 / (double)MM);
        double var  = Ss[c]  * (1.0 / (double)MM) - mean * mean;
        float s = gamma[c] * rsqrtf((float)var + BNEPS);
        sc[c]  = s;
        shf[c] = beta[c] - (float)mean * s;
    }
}

__global__ void act_kernel(float* __restrict__ Y,
                           const float* __restrict__ sc,
                           const float* __restrict__ shf) {
    int i = blockIdx.x * blockDim.x + threadIdx.x;
    float4 v = ((float4*)Y)[i];
    const float4 s4 = ((const float4*)sc)[i & 31];   // H1/4 = 32
    const float4 t4 = ((const float4*)shf)[i & 31];
    v.x = fmaxf(0.0f, fmaf(v.x, s4.x, t4.x));
    v.y = fmaxf(0.0f, fmaf(v.y, s4.y, t4.y));
    v.z = fmaxf(0.0f, fmaf(v.z, s4.z, t4.z));
    v.w = fmaxf(0.0f, fmaf(v.w, s4.w, t4.w));
    ((float4*)Y)[i] = v;
}

// ---------------------------------------------------------------------------
// Launch sequence
// ---------------------------------------------------------------------------
extern "C" void kernel_launch(void* const* d_in, const int* in_sizes, int n_in,
                              void* d_out, int out_size) {
    const float* xyz1    = (const float*)d_in[0];
    const float* xyz2    = (const float*)d_in[1];
    const float* points1 = (const float*)d_in[2];
    const float* points2 = (const float*)d_in[3];
    const float* rel_w   = (const float*)d_in[4];
    const float* rel_b   = (const float*)d_in[5];
    const float* W0      = (const float*)d_in[6];
    const float* b0      = (const float*)d_in[7];
    const float* g0      = (const float*)d_in[8];
    const float* be0     = (const float*)d_in[9];
    const float* W1      = (const float*)d_in[10];
    const float* b1      = (const float*)d_in[11];
    const float* g1      = (const float*)d_in[12];
    const float* be1     = (const float*)d_in[13];
    float* out = (float*)d_out;

    float *p_y0, *p_w0t, *p_w1t, *p_s0, *p_t0, *p_s1, *p_t1;
    double *p_sum0, *p_ss0, *p_sum1, *p_ss1;
    cudaGetSymbolAddress((void**)&p_y0,   g_y0);
    cudaGetSymbolAddress((void**)&p_w0t,  g_w0t);
    cudaGetSymbolAddress((void**)&p_w1t,  g_w1t);
    cudaGetSymbolAddress((void**)&p_s0,   g_s0);
    cudaGetSymbolAddress((void**)&p_t0,   g_t0);
    cudaGetSymbolAddress((void**)&p_s1,   g_s1);
    cudaGetSymbolAddress((void**)&p_t1,   g_t1);
    cudaGetSymbolAddress((void**)&p_sum0, g_sum0);
    cudaGetSymbolAddress((void**)&p_ss0,  g_ss0);
    cudaGetSymbolAddress((void**)&p_sum1, g_sum1);
    cudaGetSymbolAddress((void**)&p_ss1,  g_ss1);

    const int smem0 = (64 + H0) * 36 * 4 * 2;     // 92160 B (2 stages)
    const int smem1 = 2 * 2 * 128 * 36 * 4;       // 73728 B
    cudaFuncSetAttribute(gemm0_kernel,
                         cudaFuncAttributeMaxDynamicSharedMemorySize, smem0);
    cudaFuncSetAttribute(gemm1_kernel,
                         cudaFuncAttributeMaxDynamicSharedMemorySize, smem1);

    zero_stats_kernel<<<1, 256>>>();
    convert_w_kernel<<<(H0 * K0 + 255) / 256, 256>>>(W0, W1);
    knn_kernel<<<dim3(NN / 256, BB), 128>>>(xyz1, xyz2, rel_w, rel_b);

    // layer 0 (interp + concat + stats fused), 64-row tiles, 2 CTAs/SM
    gemm0_kernel<<<MM / 64, 256, smem0>>>(points1, points2, p_w0t, b0,
                                          p_y0, p_sum0, p_ss0);
    finalize_kernel<<<1, H0>>>(p_sum0, p_ss0, g0, be0, p_s0, p_t0, H0);

    // layer 1 (BN0+ReLU fused on A, stats fused on output)
    gemm1_kernel<<<MM / 128, 256, smem1>>>(p_y0, p_w1t, b1, p_s0, p_t0, out,
                                           p_sum1, p_ss1);
    finalize_kernel<<<1, H1>>>(p_sum1, p_ss1, g1, be1, p_s1, p_t1, H1);

    act_kernel<<<(MM * H1 / 4) / 256, 256>>>(out, p_s1, p_t1);
}